// round 5
// baseline (speedup 1.0000x reference)
#include <cuda_runtime.h>
#include <math.h>
#include <stdint.h>

#define BT 32
#define DIM 64
#define HW 4096
#define N2 131072
#define IMOFF 8388608
#define LNEPS 1e-5f

// ---------------- scratch ----------------
__device__ __align__(16) float g_xc[(size_t)BT * HW * 128];   // LN'd conv input (pixel-major, tf32-rounded)
__device__ __align__(16) float g_x1r[(size_t)BT * DIM * HW];
__device__ __align__(16) float g_x1i[(size_t)BT * DIM * HW];
__device__ __align__(16) float g_u[(size_t)8192 * 16 * 128];  // u then h in-place, [n][t][128]
__device__ float g_ar[BT * DIM], g_ai[BT * DIM], g_fr[BT * DIM], g_fi[BT * DIM], g_sq[BT];

__device__ __forceinline__ float gelu_tanh(float x) {
    float t = 0.7978845608028654f * (x + 0.044715f * x * x * x);
    return 0.5f * x * (1.0f + tanhf(t));
}
__device__ __forceinline__ float4 ld4(const float* p) { return *(const float4*)p; }
__device__ __forceinline__ uint32_t f2tf32(float f) {
    uint32_t u; asm("cvt.rna.tf32.f32 %0, %1;" : "=r"(u) : "f"(f)); return u;
}
__device__ __forceinline__ void mma_tf32(float4& c, uint32_t a0, uint32_t a1, uint32_t a2,
                                         uint32_t a3, uint32_t b0, uint32_t b1) {
    asm volatile("mma.sync.aligned.m16n8k8.row.col.f32.tf32.tf32.f32 "
                 "{%0,%1,%2,%3}, {%4,%5,%6,%7}, {%8,%9}, {%0,%1,%2,%3};"
                 : "+f"(c.x), "+f"(c.y), "+f"(c.z), "+f"(c.w)
                 : "r"(a0), "r"(a1), "r"(a2), "r"(a3), "r"(b0), "r"(b1));
}

// ---------------- K0: per-(b,t,d) decay & forcing ----------------
__global__ void k_setup(const float* __restrict__ dt, const float* __restrict__ lam_re,
                        const float* __restrict__ lam_im) {
    int i = blockIdx.x * blockDim.x + threadIdx.x;
    if (i >= BT * DIM) return;
    int bt = i >> 6, d = i & 63;
    float dtv = dt[bt];
    float x = lam_re[d];
    float sp = (x > 20.f) ? x : log1pf(expf(x));
    float lr = -sp, li = lam_im[d];
    float er = expf(lr * dtv);
    float ar = er * cosf(li * dtv), ai = er * sinf(li * dtv);
    float den = lr * lr + li * li;
    g_ar[i] = ar; g_ai[i] = ai;
    g_fr[i] = ((ar - 1.f) * lr + ai * li) / den;
    g_fi[i] = (ai * lr - (ar - 1.f) * li) / den;
    if (d == 0) g_sq[bt] = 0.01f * sqrtf(dtv);
}

// ---------------- K1: spatial complex LayerNorm -> g_xc (tf32-rounded) ----------------
__global__ void k_sln(const float* __restrict__ xr, const float* __restrict__ xi,
                      const float* __restrict__ w, const float* __restrict__ b) {
    __shared__ float sh[128][65];
    __shared__ float smu[64], srs[64];
    int t = threadIdx.x;
    int p0 = blockIdx.x * 64;
    int bt = p0 >> 12, hw0 = p0 & 4095;
    for (int r = 0; r < 32; r++) {
        int idx = t + 256 * r;
        int c = idx >> 6, p = idx & 63;
        float v = (c < 64) ? xr[((size_t)(bt * 64 + c)) * 4096 + hw0 + p]
                           : xi[((size_t)(bt * 64 + c - 64)) * 4096 + hw0 + p];
        sh[c][p] = v;
    }
    __syncthreads();
    int wid = t >> 5, lane = t & 31;
    if (wid < 8) {
        for (int pp = 0; pp < 8; pp++) {
            int p = wid * 8 + pp;
            float s = 0.f, s2 = 0.f;
            for (int cc = lane; cc < 128; cc += 32) {
                float v = sh[cc][p]; s += v; s2 += v * v;
            }
            for (int o = 16; o; o >>= 1) {
                s += __shfl_xor_sync(0xffffffffu, s, o);
                s2 += __shfl_xor_sync(0xffffffffu, s2, o);
            }
            if (lane == 0) {
                float mu = s * (1.f / 128.f);
                smu[p] = mu;
                srs[p] = rsqrtf(s2 * (1.f / 128.f) - mu * mu + LNEPS);
            }
        }
    }
    __syncthreads();
    for (int r = 0; r < 32; r++) {
        int idx = t + 256 * r;
        int p = idx >> 7, c = idx & 127;
        float v = (sh[c][p] - smu[p]) * srs[p] * w[c] + b[c];
        g_xc[((size_t)(p0 + p)) * 128 + c] = __uint_as_float(f2tf32(v));
    }
}

// ---------------- K2: 3x3 conv via tf32 mma, + bias + residual -> x1 ----------------
#define CONV_ASTR 36
#define CONV_BSTR 136
__global__ void k_conv(const float* __restrict__ cw, const float* __restrict__ cb,
                       const float* __restrict__ xr, const float* __restrict__ xi) {
    extern __shared__ uint32_t cs[];
    uint32_t* A = cs;                  // [264][36]
    uint32_t* B = cs + 264 * CONV_ASTR;// [32][136]
    float* Cst = (float*)cs;           // epilogue stage [128 co][130]
    int t = threadIdx.x;
    int h0 = blockIdx.x * 2, bt = blockIdx.y;
    int wrp = t >> 5, lane = t & 31;
    int wm = wrp & 3, wn = wrp >> 2;
    int qr = lane >> 2, qc = lane & 3;
    float4 acc[2][8];
#pragma unroll
    for (int i = 0; i < 2; i++)
#pragma unroll
        for (int j = 0; j < 8; j++) acc[i][j] = make_float4(0, 0, 0, 0);

    for (int kc = 0; kc < 4; kc++) {
        int ci0 = kc * 32;
        __syncthreads();
        for (int r = 0; r < 4; r++) {
            int gh = h0 + r - 1;
            for (int idx = t; idx < 2112; idx += 256) {
                int xx = idx >> 5, c = idx & 31;
                int gw = xx - 1;
                float v = 0.f;
                if ((unsigned)gh < 64u && (unsigned)gw < 64u)
                    v = g_xc[((size_t)(bt * 4096 + gh * 64 + gw)) * 128 + ci0 + c];
                A[(r * 66 + xx) * CONV_ASTR + c] = __float_as_uint(v);
            }
        }
        for (int tap = 0; tap < 9; tap++) {
            int dy = tap / 3 - 1, dx = tap % 3 - 1;
            __syncthreads();
            for (int idx = t; idx < 4096; idx += 256) {
                int kk = idx >> 7, co = idx & 127;
                B[kk * CONV_BSTR + co] = f2tf32(cw[((size_t)(tap * 128 + ci0 + kk)) * 128 + co]);
            }
            __syncthreads();
            int prs[4];
#pragma unroll
            for (int i = 0; i < 4; i++) {
                int m = wm * 32 + i * 8 + qr;
                int y = m >> 6, x = m & 63;
                prs[i] = (y + dy + 1) * 66 + (x + dx + 1);
            }
#pragma unroll
            for (int ks = 0; ks < 4; ks++) {
                int acol = ks * 8 + qc;
                uint32_t af[4][2];
#pragma unroll
                for (int i = 0; i < 4; i++) {
                    af[i][0] = A[prs[i] * CONV_ASTR + acol];
                    af[i][1] = A[prs[i] * CONV_ASTR + acol + 4];
                }
                int brow0 = (ks * 8 + qc) * CONV_BSTR;
                int brow1 = brow0 + 4 * CONV_BSTR;
#pragma unroll
                for (int nt = 0; nt < 8; nt++) {
                    int co = wn * 64 + nt * 8 + qr;
                    uint32_t b0 = B[brow0 + co], b1 = B[brow1 + co];
                    mma_tf32(acc[0][nt], af[0][0], af[1][0], af[0][1], af[1][1], b0, b1);
                    mma_tf32(acc[1][nt], af[2][0], af[3][0], af[2][1], af[3][1], b0, b1);
                }
            }
        }
    }
    __syncthreads();
#pragma unroll
    for (int mt = 0; mt < 2; mt++)
#pragma unroll
        for (int nt = 0; nt < 8; nt++) {
            int m0 = wm * 32 + mt * 16 + qr;
            int n0 = wn * 64 + nt * 8 + 2 * qc;
            float4 c = acc[mt][nt];
            Cst[n0 * 130 + m0] = c.x;
            Cst[(n0 + 1) * 130 + m0] = c.y;
            Cst[n0 * 130 + m0 + 8] = c.z;
            Cst[(n0 + 1) * 130 + m0 + 8] = c.w;
        }
    __syncthreads();
    int p = t & 127, og = t >> 7;
    size_t pb = (size_t)h0 * 64 + p;
    for (int j = 0; j < 64; j++) {
        int co = og * 64 + j;
        float v = Cst[co * 130 + p] + cb[co];
        if (co < 64) {
            size_t gi = ((size_t)(bt * 64 + co)) * 4096 + pb;
            g_x1r[gi] = v + xr[gi];
        } else {
            size_t gi = ((size_t)(bt * 64 + co - 64)) * 4096 + pb;
            g_x1i[gi] = v + xi[gi];
        }
    }
}

// ---------------- K3a: temporal LN + encode (tf32 mma) + forcing + noise -> g_u ----------------
// block = 128 tokens (one bt) x 128 outputs. LN fused; raw-fp32 operands (HW truncates to tf32).
#define ENC_ASTR 132
#define ENC_BSTR 136
__global__ __launch_bounds__(256, 1) void k_enc(
        const float* __restrict__ ltw, const float* __restrict__ ltb,
        const float* __restrict__ encr, const float* __restrict__ enci,
        const float* __restrict__ sbr, const float* __restrict__ sbi,
        const float* __restrict__ nzr, const float* __restrict__ nzi) {
    extern __shared__ uint32_t es[];
    uint32_t* A = es;                        // [128 tok][132 k]
    uint32_t* B = es + 128 * ENC_ASTR;       // [128 k][136 j]
    float* smu = (float*)(es + 128 * ENC_ASTR + 128 * ENC_BSTR);
    float* srs = smu + 128;
    float* Af = (float*)A;
    float* Cst = (float*)A;                  // stage reuses A after mma
    int t = threadIdx.x;
    int t0 = blockIdx.x * 128;
    int bt = t0 >> 12, hw0 = t0 & 4095;
    int b = bt >> 4, tt = bt & 15;
    int wrp = t >> 5, lane = t & 31;
    int wm = wrp & 3, wn = wrp >> 2;
    int qr = lane >> 2, qc = lane & 3;

    // load x1 tile -> A[tok][k] (fp32)
    for (int r = 0; r < 64; r++) {
        int idx = t + 256 * r;
        int c = idx >> 7, tl = idx & 127;
        float v = (c < 64) ? g_x1r[((size_t)(bt * 64 + c)) * 4096 + hw0 + tl]
                           : g_x1i[((size_t)(bt * 64 + c - 64)) * 4096 + hw0 + tl];
        Af[tl * ENC_ASTR + c] = v;
    }
    // pack B: [k][j]  j<64: real out, j>=64: imag out
    for (int r = 0; r < 64; r++) {
        int idx = t + 256 * r;
        int k = idx >> 7, j = idx & 127;
        float v;
        if (k < 64) v = (j < 64) ? encr[k * 64 + j] : enci[k * 64 + (j - 64)];
        else        v = (j < 64) ? -enci[(k - 64) * 64 + j] : encr[(k - 64) * 64 + (j - 64)];
        B[k * ENC_BSTR + j] = __float_as_uint(v);
    }
    __syncthreads();
    // LN stats: 8 warps x 16 tokens
    for (int sub = 0; sub < 16; sub++) {
        int tok = wrp * 16 + sub;
        float s = 0.f, s2 = 0.f;
        for (int k = lane; k < 128; k += 32) {
            float v = Af[tok * ENC_ASTR + k]; s += v; s2 += v * v;
        }
        for (int o = 16; o; o >>= 1) {
            s += __shfl_xor_sync(0xffffffffu, s, o);
            s2 += __shfl_xor_sync(0xffffffffu, s2, o);
        }
        if (lane == 0) {
            float mu = s * (1.f / 128.f);
            smu[tok] = mu;
            srs[tok] = rsqrtf(s2 * (1.f / 128.f) - mu * mu + LNEPS);
        }
    }
    __syncthreads();
    for (int r = 0; r < 64; r++) {
        int idx = t + 256 * r;
        int tok = idx >> 7, k = idx & 127;
        Af[tok * ENC_ASTR + k] = (Af[tok * ENC_ASTR + k] - smu[tok]) * srs[tok] * ltw[k] + ltb[k];
    }
    __syncthreads();
    // mma 128x128x128
    float4 acc[2][8];
#pragma unroll
    for (int i = 0; i < 2; i++)
#pragma unroll
        for (int j = 0; j < 8; j++) acc[i][j] = make_float4(0, 0, 0, 0);
#pragma unroll
    for (int ks = 0; ks < 16; ks++) {
        int acol = ks * 8 + qc;
        uint32_t af[4][2];
#pragma unroll
        for (int i = 0; i < 4; i++) {
            int row = wm * 32 + i * 8 + qr;
            af[i][0] = A[row * ENC_ASTR + acol];
            af[i][1] = A[row * ENC_ASTR + acol + 4];
        }
        int br0 = (ks * 8 + qc) * ENC_BSTR, br1 = br0 + 4 * ENC_BSTR;
#pragma unroll
        for (int nt = 0; nt < 8; nt++) {
            int j = wn * 64 + nt * 8 + qr;
            uint32_t b0 = B[br0 + j], b1 = B[br1 + j];
            mma_tf32(acc[0][nt], af[0][0], af[1][0], af[0][1], af[1][1], b0, b1);
            mma_tf32(acc[1][nt], af[2][0], af[3][0], af[2][1], af[3][1], b0, b1);
        }
    }
    __syncthreads();
#pragma unroll
    for (int mt = 0; mt < 2; mt++)
#pragma unroll
        for (int nt = 0; nt < 8; nt++) {
            int tok0 = wm * 32 + mt * 16 + qr;
            int j0 = wn * 64 + nt * 8 + 2 * qc;
            float4 c = acc[mt][nt];
            Cst[j0 * 130 + tok0] = c.x;
            Cst[(j0 + 1) * 130 + tok0] = c.y;
            Cst[j0 * 130 + tok0 + 8] = c.z;
            Cst[(j0 + 1) * 130 + tok0 + 8] = c.w;
        }
    __syncthreads();
    // epilogue: bias + forcing + noise -> g_u
    int e = t & 63, tg = t >> 6;
    int ai_ = bt * 64 + e;
    float fr = g_fr[ai_], fi_ = g_fi[ai_], sq = g_sq[bt];
    float sbrv = sbr[e], sbiv = sbi[e];
    for (int k = 0; k < 32; k++) {
        int tk = tg * 32 + k;
        int n = b * 4096 + hw0 + tk;
        size_t ub = ((size_t)n * 16 + tt) * 128;
        float ur = Cst[e * 130 + tk] + sbrv;
        float ui = Cst[(e + 64) * 130 + tk] + sbiv;
        size_t nb = ((size_t)n * 16 + tt) * 64 + e;
        g_u[ub + e]      = ur * fr - ui * fi_ + sq * nzr[nb];
        g_u[ub + 64 + e] = ur * fi_ + ui * fr + sq * nzi[nb];
    }
}

// ---------------- K3b: in-place 16-step scan over g_u ----------------
__global__ void k_scan() {
    int t = threadIdx.x;
    int e = t & 63;
    int n = blockIdx.x * 4 + (t >> 6);
    int b = n >> 12;
    float hr = 0.f, hi = 0.f;
    for (int tt = 0; tt < 16; tt++) {
        size_t base = ((size_t)n * 16 + tt) * 128;
        float ur = g_u[base + e], ui = g_u[base + 64 + e];
        int ai_ = (b * 16 + tt) * 64 + e;
        float ar = g_ar[ai_], aiv = g_ai[ai_];
        float nhr = ar * hr - aiv * hi + ur;
        float nhi = ar * hi + aiv * hr + ui;
        hr = nhr; hi = nhi;
        g_u[base + e] = hr; g_u[base + 64 + e] = hi;
    }
}

// ---------------- K4: fused decode + residual + MoE -> d_out ----------------
// block = 128 tokens. dec mma (128x64x128) -> drift; tokens fp32 in smem; gates;
// MoE GEMM1/gelu/GEMM2 (tf32 mma, fp32 operands truncated by HW); single out write.
#define DO_ASTR 132
#define DO_BSTR 136
__global__ __launch_bounds__(256, 1) void k_out(
        const float* __restrict__ decr, const float* __restrict__ deci,
        const float* __restrict__ rw, const float* __restrict__ rb,
        const float* __restrict__ w1, const float* __restrict__ b1,
        const float* __restrict__ w2, const float* __restrict__ b2,
        float* __restrict__ out) {
    extern __shared__ uint32_t os[];
    uint32_t* AU  = os;                       // [128][132]: g_u tile -> later HS -> later Cst
    uint32_t* TOK = os + 16896;               // [128][132]: fp32 tokens
    uint32_t* Bm  = os + 2 * 16896;           // 9216 words: dec B [128][72] / Dst [64][130] / moe B [32][136]
    float* G      = (float*)(os + 2 * 16896 + 9216);  // [4][128]
    float* AUf = (float*)AU;
    float* TOKf = (float*)TOK;
    float* Bmf = (float*)Bm;
    int t = threadIdx.x;
    int t0 = blockIdx.x * 128;
    int bt = t0 >> 12, hw0 = t0 & 4095;
    int b = bt >> 4, tt = bt & 15;
    int wrp = t >> 5, lane = t & 31;
    int wm = wrp & 3, wn = wrp >> 2;
    int qr = lane >> 2, qc = lane & 3;

    // 1. load h tile -> AU[tok][k]
    for (int r = 0; r < 16; r++) {
        int idx = t + 256 * r;
        int tok = idx >> 5, k4 = idx & 31;
        float4 v = ld4(&g_u[((size_t)(b * 4096 + hw0 + tok) * 16 + tt) * 128 + k4 * 4]);
        *(float4*)&AUf[tok * DO_ASTR + k4 * 4] = v;
    }
    // 2. dec B [k 128][d 64] stride 72 (real part extraction)
    for (int r = 0; r < 32; r++) {
        int idx = t + 256 * r;
        int k = idx >> 6, d = idx & 63;
        float v = (k < 64) ? decr[k * 64 + d] : -deci[(k - 64) * 64 + d];
        Bmf[k * 72 + d] = v;
    }
    __syncthreads();
    // 3. dec mma: 128 tok x 64 d x 128 k
    {
        float4 dacc[2][4];
#pragma unroll
        for (int i = 0; i < 2; i++)
#pragma unroll
            for (int j = 0; j < 4; j++) dacc[i][j] = make_float4(0, 0, 0, 0);
#pragma unroll
        for (int ks = 0; ks < 16; ks++) {
            int acol = ks * 8 + qc;
            uint32_t af[4][2];
#pragma unroll
            for (int i = 0; i < 4; i++) {
                int row = wm * 32 + i * 8 + qr;
                af[i][0] = AU[row * DO_ASTR + acol];
                af[i][1] = AU[row * DO_ASTR + acol + 4];
            }
            int br0 = (ks * 8 + qc) * 72, br1 = br0 + 4 * 72;
#pragma unroll
            for (int nt = 0; nt < 4; nt++) {
                int j = wn * 32 + nt * 8 + qr;
                uint32_t b0 = Bm[br0 + j], b1v = Bm[br1 + j];
                mma_tf32(dacc[0][nt], af[0][0], af[1][0], af[0][1], af[1][1], b0, b1v);
                mma_tf32(dacc[1][nt], af[2][0], af[3][0], af[2][1], af[3][1], b0, b1v);
            }
        }
        __syncthreads();
        // stage drift -> Dst[d][tok] (reuses Bm)
#pragma unroll
        for (int mt = 0; mt < 2; mt++)
#pragma unroll
            for (int nt = 0; nt < 4; nt++) {
                int tok0 = wm * 32 + mt * 16 + qr;
                int d0 = wn * 32 + nt * 8 + 2 * qc;
                float4 c = dacc[mt][nt];
                Bmf[d0 * 130 + tok0] = c.x;
                Bmf[(d0 + 1) * 130 + tok0] = c.y;
                Bmf[d0 * 130 + tok0 + 8] = c.z;
                Bmf[(d0 + 1) * 130 + tok0 + 8] = c.w;
            }
    }
    __syncthreads();
    // 4. build fp32 tokens: real = x1r + drift, imag = x1i
    for (int r = 0; r < 64; r++) {
        int idx = t + 256 * r;
        int c = idx >> 7, tl = idx & 127;
        float v;
        if (c < 64) v = g_x1r[((size_t)(bt * 64 + c)) * 4096 + hw0 + tl] + Bmf[c * 130 + tl];
        else        v = g_x1i[((size_t)(bt * 64 + c - 64)) * 4096 + hw0 + tl];
        TOKf[tl * DO_ASTR + c] = v;
    }
    __syncthreads();
    // 5. gates
    if (t < 128) {
        float l0 = rb[0], l1 = rb[1], l2 = rb[2], l3 = rb[3];
        for (int c = 0; c < 128; c++) {
            float v = TOKf[t * DO_ASTR + c];
            float4 wv = ld4(rw + c * 4);
            l0 = fmaf(v, wv.x, l0); l1 = fmaf(v, wv.y, l1);
            l2 = fmaf(v, wv.z, l2); l3 = fmaf(v, wv.w, l3);
        }
        float m = fmaxf(fmaxf(l0, l1), fmaxf(l2, l3));
        float e0 = expf(l0 - m), e1 = expf(l1 - m), e2 = expf(l2 - m), e3 = expf(l3 - m);
        float inv = 1.f / (e0 + e1 + e2 + e3);
        G[0 * 128 + t] = e0 * inv; G[1 * 128 + t] = e1 * inv;
        G[2 * 128 + t] = e2 * inv; G[3 * 128 + t] = e3 * inv;
    }
    // 6. MoE
    float4 acc2[2][8];
#pragma unroll
    for (int i = 0; i < 2; i++)
#pragma unroll
        for (int j = 0; j < 8; j++) acc2[i][j] = make_float4(0, 0, 0, 0);

    for (int e = 0; e < 4; e++) {
        float4 acc1[2][8];
#pragma unroll
        for (int i = 0; i < 2; i++)
#pragma unroll
            for (int j = 0; j < 8; j++) acc1[i][j] = make_float4(0, 0, 0, 0);
        // GEMM1: TOK @ w1[e]
        for (int kc = 0; kc < 4; kc++) {
            int ci0 = kc * 32;
            __syncthreads();
            for (int idx = t; idx < 4096; idx += 256) {
                int kk = idx >> 7, j = idx & 127;
                Bm[kk * DO_BSTR + j] = f2tf32(w1[(size_t)e * 16384 + (ci0 + kk) * 128 + j]);
            }
            __syncthreads();
#pragma unroll
            for (int ks = 0; ks < 4; ks++) {
                int acol = ci0 + ks * 8 + qc;
                uint32_t af[4][2];
#pragma unroll
                for (int i = 0; i < 4; i++) {
                    int row = wm * 32 + i * 8 + qr;
                    af[i][0] = TOK[row * DO_ASTR + acol];
                    af[i][1] = TOK[row * DO_ASTR + acol + 4];
                }
                int br0 = (ks * 8 + qc) * DO_BSTR, br1 = br0 + 4 * DO_BSTR;
#pragma unroll
                for (int nt = 0; nt < 8; nt++) {
                    int j = wn * 64 + nt * 8 + qr;
                    uint32_t b0 = Bm[br0 + j], b1v = Bm[br1 + j];
                    mma_tf32(acc1[0][nt], af[0][0], af[1][0], af[0][1], af[1][1], b0, b1v);
                    mma_tf32(acc1[1][nt], af[2][0], af[3][0], af[2][1], af[3][1], b0, b1v);
                }
            }
        }
        __syncthreads();
        // epilogue1: bias + gelu * gate -> HS (fp32; HW truncates at mma)
#pragma unroll
        for (int mt = 0; mt < 2; mt++)
#pragma unroll
            for (int nt = 0; nt < 8; nt++) {
                int tok0 = wm * 32 + mt * 16 + qr;
                int j0 = wn * 64 + nt * 8 + 2 * qc;
                float4 c = acc1[mt][nt];
                float b1v0 = b1[e * 128 + j0], b1v1 = b1[e * 128 + j0 + 1];
                float g0 = G[e * 128 + tok0], g8 = G[e * 128 + tok0 + 8];
                AUf[tok0 * DO_ASTR + j0]           = gelu_tanh(c.x + b1v0) * g0;
                AUf[tok0 * DO_ASTR + j0 + 1]       = gelu_tanh(c.y + b1v1) * g0;
                AUf[(tok0 + 8) * DO_ASTR + j0]     = gelu_tanh(c.z + b1v0) * g8;
                AUf[(tok0 + 8) * DO_ASTR + j0 + 1] = gelu_tanh(c.w + b1v1) * g8;
            }
        // GEMM2: HS @ w2[e] -> acc2
        for (int kc = 0; kc < 4; kc++) {
            int ci0 = kc * 32;
            __syncthreads();
            for (int idx = t; idx < 4096; idx += 256) {
                int kk = idx >> 7, j = idx & 127;
                Bm[kk * DO_BSTR + j] = f2tf32(w2[(size_t)e * 16384 + (ci0 + kk) * 128 + j]);
            }
            __syncthreads();
#pragma unroll
            for (int ks = 0; ks < 4; ks++) {
                int acol = ci0 + ks * 8 + qc;
                uint32_t af[4][2];
#pragma unroll
                for (int i = 0; i < 4; i++) {
                    int row = wm * 32 + i * 8 + qr;
                    af[i][0] = AU[row * DO_ASTR + acol];
                    af[i][1] = AU[row * DO_ASTR + acol + 4];
                }
                int br0 = (ks * 8 + qc) * DO_BSTR, br1 = br0 + 4 * DO_BSTR;
#pragma unroll
                for (int nt = 0; nt < 8; nt++) {
                    int j = wn * 64 + nt * 8 + qr;
                    uint32_t b0 = Bm[br0 + j], b1v = Bm[br1 + j];
                    mma_tf32(acc2[0][nt], af[0][0], af[1][0], af[0][1], af[1][1], b0, b1v);
                    mma_tf32(acc2[1][nt], af[2][0], af[3][0], af[2][1], af[3][1], b0, b1v);
                }
            }
        }
    }
    __syncthreads();
    // 7. stage acc2 -> Cst (reuses AU region)
    float* Cst = AUf;
#pragma unroll
    for (int mt = 0; mt < 2; mt++)
#pragma unroll
        for (int nt = 0; nt < 8; nt++) {
            int tok0 = wm * 32 + mt * 16 + qr;
            int o0 = wn * 64 + nt * 8 + 2 * qc;
            float4 c = acc2[mt][nt];
            Cst[o0 * 130 + tok0] = c.x;
            Cst[(o0 + 1) * 130 + tok0] = c.y;
            Cst[o0 * 130 + tok0 + 8] = c.z;
            Cst[(o0 + 1) * 130 + tok0 + 8] = c.w;
        }
    __syncthreads();
    // 8. final write: out = token + delta
    int tl = t & 127, og = t >> 7;
    float g0 = G[tl], g1 = G[128 + tl], g2 = G[256 + tl], g3 = G[384 + tl];
    for (int j = 0; j < 64; j++) {
        int o = og * 64 + j;
        float delta = Cst[o * 130 + tl] +
                      g0 * b2[o] + g1 * b2[128 + o] + g2 * b2[256 + o] + g3 * b2[384 + o];
        float tokv = TOKf[tl * DO_ASTR + o];
        size_t gi = (o < 64) ? ((size_t)(bt * 64 + o)) * 4096 + hw0 + tl
                             : IMOFF + ((size_t)(bt * 64 + o - 64)) * 4096 + hw0 + tl;
        out[gi] = tokv + delta;
    }
}

extern "C" void kernel_launch(void* const* d_in, const int* in_sizes, int n_in,
                              void* d_out, int out_size) {
    const float* x_real = (const float*)d_in[0];
    const float* x_imag = (const float*)d_in[1];
    const float* dt     = (const float*)d_in[2];
    const float* nz_r   = (const float*)d_in[3];
    const float* nz_i   = (const float*)d_in[4];
    const float* ln_s_w = (const float*)d_in[5];
    const float* ln_s_b = (const float*)d_in[6];
    const float* conv_w = (const float*)d_in[7];
    const float* conv_b = (const float*)d_in[8];
    const float* ln_t_w = (const float*)d_in[9];
    const float* ln_t_b = (const float*)d_in[10];
    const float* lam_re = (const float*)d_in[11];
    const float* lam_im = (const float*)d_in[12];
    const float* sb_re  = (const float*)d_in[13];
    const float* sb_im  = (const float*)d_in[14];
    const float* enc_re = (const float*)d_in[15];
    const float* enc_im = (const float*)d_in[16];
    const float* dec_re = (const float*)d_in[17];
    const float* dec_im = (const float*)d_in[18];
    const float* rw     = (const float*)d_in[19];
    const float* rb     = (const float*)d_in[20];
    const float* w1     = (const float*)d_in[21];
    const float* b1     = (const float*)d_in[22];
    const float* w2     = (const float*)d_in[23];
    const float* b2     = (const float*)d_in[24];
    float* out = (float*)d_out;

    int conv_smem = 128 * 130 * 4;                                     // 66560 B
    int enc_smem  = (128 * ENC_ASTR + 128 * ENC_BSTR + 256) * 4;       // 138240 B
    int out_smem  = (2 * 16896 + 9216 + 512) * 4;                      // 174080 B
    cudaFuncSetAttribute(k_conv, cudaFuncAttributeMaxDynamicSharedMemorySize, conv_smem);
    cudaFuncSetAttribute(k_enc, cudaFuncAttributeMaxDynamicSharedMemorySize, enc_smem);
    cudaFuncSetAttribute(k_out, cudaFuncAttributeMaxDynamicSharedMemorySize, out_smem);

    k_setup<<<8, 256>>>(dt, lam_re, lam_im);
    k_sln<<<2048, 256>>>(x_real, x_imag, ln_s_w, ln_s_b);
    k_conv<<<dim3(32, 32), 256, conv_smem>>>(conv_w, conv_b, x_real, x_imag);
    k_enc<<<1024, 256, enc_smem>>>(ln_t_w, ln_t_b, enc_re, enc_im, sb_re, sb_im, nz_r, nz_i);
    k_scan<<<2048, 256>>>();
    k_out<<<1024, 256, out_smem>>>(dec_re, dec_im, rw, rb, w1, b1, w2, b2, out);
}

// round 6
// speedup vs baseline: 1.4728x; 1.4728x over previous
#include <cuda_runtime.h>
#include <math.h>
#include <stdint.h>

#define BT 32
#define DIM 64
#define HW 4096
#define N2 131072
#define IMOFF 8388608
#define LNEPS 1e-5f

// ---------------- scratch ----------------
__device__ __align__(16) float g_xc[(size_t)BT * HW * 128];   // LN'd conv input (pixel-major, tf32-rounded)
__device__ __align__(16) float g_x1r[(size_t)BT * DIM * HW];
__device__ __align__(16) float g_x1i[(size_t)BT * DIM * HW];
__device__ __align__(16) float g_u[(size_t)8192 * 16 * 128];  // u then h in-place, [n][t][128]
__device__ float g_ar[BT * DIM], g_ai[BT * DIM], g_fr[BT * DIM], g_fi[BT * DIM], g_sq[BT];

__device__ __forceinline__ float gelu_tanh(float x) {
    float t = 0.7978845608028654f * (x + 0.044715f * x * x * x);
    return 0.5f * x * (1.0f + tanhf(t));
}
__device__ __forceinline__ void fma4(float4& a, float s, float4 w) {
    a.x = fmaf(s, w.x, a.x); a.y = fmaf(s, w.y, a.y);
    a.z = fmaf(s, w.z, a.z); a.w = fmaf(s, w.w, a.w);
}
__device__ __forceinline__ float4 ld4(const float* p) { return *(const float4*)p; }
__device__ __forceinline__ float4 neg4(float4 v) { return make_float4(-v.x, -v.y, -v.z, -v.w); }
__device__ __forceinline__ uint32_t f2tf32(float f) {
    uint32_t u; asm("cvt.rna.tf32.f32 %0, %1;" : "=r"(u) : "f"(f)); return u;
}
__device__ __forceinline__ void mma_tf32(float4& c, uint32_t a0, uint32_t a1, uint32_t a2,
                                         uint32_t a3, uint32_t b0, uint32_t b1) {
    asm volatile("mma.sync.aligned.m16n8k8.row.col.f32.tf32.tf32.f32 "
                 "{%0,%1,%2,%3}, {%4,%5,%6,%7}, {%8,%9}, {%0,%1,%2,%3};"
                 : "+f"(c.x), "+f"(c.y), "+f"(c.z), "+f"(c.w)
                 : "r"(a0), "r"(a1), "r"(a2), "r"(a3), "r"(b0), "r"(b1));
}

// ---------------- K0: per-(b,t,d) decay & forcing ----------------
__global__ void k_setup(const float* __restrict__ dt, const float* __restrict__ lam_re,
                        const float* __restrict__ lam_im) {
    int i = blockIdx.x * blockDim.x + threadIdx.x;
    if (i >= BT * DIM) return;
    int bt = i >> 6, d = i & 63;
    float dtv = dt[bt];
    float x = lam_re[d];
    float sp = (x > 20.f) ? x : log1pf(expf(x));
    float lr = -sp, li = lam_im[d];
    float er = expf(lr * dtv);
    float ar = er * cosf(li * dtv), ai = er * sinf(li * dtv);
    float den = lr * lr + li * li;
    g_ar[i] = ar; g_ai[i] = ai;
    g_fr[i] = ((ar - 1.f) * lr + ai * li) / den;
    g_fi[i] = (ai * lr - (ar - 1.f) * li) / den;
    if (d == 0) g_sq[bt] = 0.01f * sqrtf(dtv);
}

// ---------------- K1: spatial complex LayerNorm -> g_xc (tf32-rounded) ----------------
__global__ void k_sln(const float* __restrict__ xr, const float* __restrict__ xi,
                      const float* __restrict__ w, const float* __restrict__ b) {
    __shared__ float sh[128][65];
    __shared__ float smu[64], srs[64];
    int t = threadIdx.x;
    int p0 = blockIdx.x * 64;
    int bt = p0 >> 12, hw0 = p0 & 4095;
    for (int r = 0; r < 32; r++) {
        int idx = t + 256 * r;
        int c = idx >> 6, p = idx & 63;
        float v = (c < 64) ? xr[((size_t)(bt * 64 + c)) * 4096 + hw0 + p]
                           : xi[((size_t)(bt * 64 + c - 64)) * 4096 + hw0 + p];
        sh[c][p] = v;
    }
    __syncthreads();
    int wid = t >> 5, lane = t & 31;
    if (wid < 8) {
        for (int pp = 0; pp < 8; pp++) {
            int p = wid * 8 + pp;
            float s = 0.f, s2 = 0.f;
            for (int cc = lane; cc < 128; cc += 32) {
                float v = sh[cc][p]; s += v; s2 += v * v;
            }
            for (int o = 16; o; o >>= 1) {
                s += __shfl_xor_sync(0xffffffffu, s, o);
                s2 += __shfl_xor_sync(0xffffffffu, s2, o);
            }
            if (lane == 0) {
                float mu = s * (1.f / 128.f);
                smu[p] = mu;
                srs[p] = rsqrtf(s2 * (1.f / 128.f) - mu * mu + LNEPS);
            }
        }
    }
    __syncthreads();
    for (int r = 0; r < 32; r++) {
        int idx = t + 256 * r;
        int p = idx >> 7, c = idx & 127;
        float v = (sh[c][p] - smu[p]) * srs[p] * w[c] + b[c];
        g_xc[((size_t)(p0 + p)) * 128 + c] = __uint_as_float(f2tf32(v));
    }
}

// ---------------- K2: 3x3 conv via tf32 mma, + bias + residual -> x1 ----------------
#define CONV_ASTR 36
#define CONV_BSTR 136
__global__ void k_conv(const float* __restrict__ cw, const float* __restrict__ cb,
                       const float* __restrict__ xr, const float* __restrict__ xi) {
    extern __shared__ uint32_t cs[];
    uint32_t* A = cs;                  // [264][36]
    uint32_t* B = cs + 264 * CONV_ASTR;// [32][136]
    float* Cst = (float*)cs;           // epilogue stage [128 co][130]
    int t = threadIdx.x;
    int h0 = blockIdx.x * 2, bt = blockIdx.y;
    int wrp = t >> 5, lane = t & 31;
    int wm = wrp & 3, wn = wrp >> 2;
    int qr = lane >> 2, qc = lane & 3;
    float4 acc[2][8];
#pragma unroll
    for (int i = 0; i < 2; i++)
#pragma unroll
        for (int j = 0; j < 8; j++) acc[i][j] = make_float4(0, 0, 0, 0);

    for (int kc = 0; kc < 4; kc++) {
        int ci0 = kc * 32;
        __syncthreads();
        for (int r = 0; r < 4; r++) {
            int gh = h0 + r - 1;
            for (int idx = t; idx < 2112; idx += 256) {
                int xx = idx >> 5, c = idx & 31;
                int gw = xx - 1;
                float v = 0.f;
                if ((unsigned)gh < 64u && (unsigned)gw < 64u)
                    v = g_xc[((size_t)(bt * 4096 + gh * 64 + gw)) * 128 + ci0 + c];
                A[(r * 66 + xx) * CONV_ASTR + c] = __float_as_uint(v);
            }
        }
        for (int tap = 0; tap < 9; tap++) {
            int dy = tap / 3 - 1, dx = tap % 3 - 1;
            __syncthreads();
            for (int idx = t; idx < 4096; idx += 256) {
                int kk = idx >> 7, co = idx & 127;
                B[kk * CONV_BSTR + co] = f2tf32(cw[((size_t)(tap * 128 + ci0 + kk)) * 128 + co]);
            }
            __syncthreads();
            int prs[4];
#pragma unroll
            for (int i = 0; i < 4; i++) {
                int m = wm * 32 + i * 8 + qr;
                int y = m >> 6, x = m & 63;
                prs[i] = (y + dy + 1) * 66 + (x + dx + 1);
            }
#pragma unroll
            for (int ks = 0; ks < 4; ks++) {
                int acol = ks * 8 + qc;
                uint32_t af[4][2];
#pragma unroll
                for (int i = 0; i < 4; i++) {
                    af[i][0] = A[prs[i] * CONV_ASTR + acol];
                    af[i][1] = A[prs[i] * CONV_ASTR + acol + 4];
                }
                int brow0 = (ks * 8 + qc) * CONV_BSTR;
                int brow1 = brow0 + 4 * CONV_BSTR;
#pragma unroll
                for (int nt = 0; nt < 8; nt++) {
                    int co = wn * 64 + nt * 8 + qr;
                    uint32_t b0 = B[brow0 + co], b1 = B[brow1 + co];
                    mma_tf32(acc[0][nt], af[0][0], af[1][0], af[0][1], af[1][1], b0, b1);
                    mma_tf32(acc[1][nt], af[2][0], af[3][0], af[2][1], af[3][1], b0, b1);
                }
            }
        }
    }
    __syncthreads();
#pragma unroll
    for (int mt = 0; mt < 2; mt++)
#pragma unroll
        for (int nt = 0; nt < 8; nt++) {
            int m0 = wm * 32 + mt * 16 + qr;
            int n0 = wn * 64 + nt * 8 + 2 * qc;
            float4 c = acc[mt][nt];
            Cst[n0 * 130 + m0] = c.x;
            Cst[(n0 + 1) * 130 + m0] = c.y;
            Cst[n0 * 130 + m0 + 8] = c.z;
            Cst[(n0 + 1) * 130 + m0 + 8] = c.w;
        }
    __syncthreads();
    int p = t & 127, og = t >> 7;
    size_t pb = (size_t)h0 * 64 + p;
    for (int j = 0; j < 64; j++) {
        int co = og * 64 + j;
        float v = Cst[co * 130 + p] + cb[co];
        if (co < 64) {
            size_t gi = ((size_t)(bt * 64 + co)) * 4096 + pb;
            g_x1r[gi] = v + xr[gi];
        } else {
            size_t gi = ((size_t)(bt * 64 + co - 64)) * 4096 + pb;
            g_x1i[gi] = v + xi[gi];
        }
    }
}

// ---------------- K3a: temporal LN + encode (tf32 mma, 512 thr) -> g_u ----------------
// block = 128 tokens x 128 out; 16 warps wm(4)x wn(4), 32tok x 32j per warp.
#define ENC_ASTR 132
#define ENC_BSTR 136
__global__ __launch_bounds__(512, 1) void k_enc(
        const float* __restrict__ ltw, const float* __restrict__ ltb,
        const float* __restrict__ encr, const float* __restrict__ enci,
        const float* __restrict__ sbr, const float* __restrict__ sbi,
        const float* __restrict__ nzr, const float* __restrict__ nzi) {
    extern __shared__ uint32_t es[];
    uint32_t* A = es;                        // [128 tok][132 k]: fp32 load -> tf32 after LN
    uint32_t* B = es + 128 * ENC_ASTR;       // [128 k][136 j] tf32
    float* smu = (float*)(es + 128 * ENC_ASTR + 128 * ENC_BSTR);
    float* srs = smu + 128;
    float* Af = (float*)A;
    float* Cst = (float*)A;                  // stage reuses A after mma
    int t = threadIdx.x;
    int t0 = blockIdx.x * 128;
    int bt = t0 >> 12, hw0 = t0 & 4095;
    int b = bt >> 4, tt = bt & 15;
    int wrp = t >> 5, lane = t & 31;
    int wm = wrp & 3, wn = wrp >> 2;
    int qr = lane >> 2, qc = lane & 3;

    // load x1 tile -> A[tok][k] (fp32)
    for (int r = 0; r < 32; r++) {
        int idx = t + 512 * r;
        int c = idx >> 7, tl = idx & 127;
        float v = (c < 64) ? g_x1r[((size_t)(bt * 64 + c)) * 4096 + hw0 + tl]
                           : g_x1i[((size_t)(bt * 64 + c - 64)) * 4096 + hw0 + tl];
        Af[tl * ENC_ASTR + c] = v;
    }
    // pack B (rna tf32): [k][j]  j<64 real out, j>=64 imag out
    for (int r = 0; r < 32; r++) {
        int idx = t + 512 * r;
        int k = idx >> 7, j = idx & 127;
        float v;
        if (k < 64) v = (j < 64) ? encr[k * 64 + j] : enci[k * 64 + (j - 64)];
        else        v = (j < 64) ? -enci[(k - 64) * 64 + j] : encr[(k - 64) * 64 + (j - 64)];
        B[k * ENC_BSTR + j] = f2tf32(v);
    }
    __syncthreads();
    // LN stats: 16 warps x 8 tokens
    for (int sub = 0; sub < 8; sub++) {
        int tok = wrp * 8 + sub;
        float s = 0.f, s2 = 0.f;
        for (int k = lane; k < 128; k += 32) {
            float v = Af[tok * ENC_ASTR + k]; s += v; s2 += v * v;
        }
        for (int o = 16; o; o >>= 1) {
            s += __shfl_xor_sync(0xffffffffu, s, o);
            s2 += __shfl_xor_sync(0xffffffffu, s2, o);
        }
        if (lane == 0) {
            float mu = s * (1.f / 128.f);
            smu[tok] = mu;
            srs[tok] = rsqrtf(s2 * (1.f / 128.f) - mu * mu + LNEPS);
        }
    }
    __syncthreads();
    // normalize + rna round in place
    for (int r = 0; r < 32; r++) {
        int idx = t + 512 * r;
        int tok = idx >> 7, k = idx & 127;
        float v = (Af[tok * ENC_ASTR + k] - smu[tok]) * srs[tok] * ltw[k] + ltb[k];
        A[tok * ENC_ASTR + k] = f2tf32(v);
    }
    __syncthreads();
    // mma 128x128x128: per warp 32tok x 32j
    float4 acc[2][4];
#pragma unroll
    for (int i = 0; i < 2; i++)
#pragma unroll
        for (int j = 0; j < 4; j++) acc[i][j] = make_float4(0, 0, 0, 0);
#pragma unroll
    for (int ks = 0; ks < 16; ks++) {
        int acol = ks * 8 + qc;
        uint32_t af[2][4];
#pragma unroll
        for (int mt = 0; mt < 2; mt++) {
            int base = (wm * 32 + mt * 16) * ENC_ASTR;
            af[mt][0] = A[base + qr * ENC_ASTR + acol];
            af[mt][1] = A[base + (qr + 8) * ENC_ASTR + acol];
            af[mt][2] = A[base + qr * ENC_ASTR + acol + 4];
            af[mt][3] = A[base + (qr + 8) * ENC_ASTR + acol + 4];
        }
        int br0 = (ks * 8 + qc) * ENC_BSTR, br1 = br0 + 4 * ENC_BSTR;
#pragma unroll
        for (int nt = 0; nt < 4; nt++) {
            int j = wn * 32 + nt * 8 + qr;
            uint32_t b0 = B[br0 + j], b1 = B[br1 + j];
            mma_tf32(acc[0][nt], af[0][0], af[0][1], af[0][2], af[0][3], b0, b1);
            mma_tf32(acc[1][nt], af[1][0], af[1][1], af[1][2], af[1][3], b0, b1);
        }
    }
    __syncthreads();
#pragma unroll
    for (int mt = 0; mt < 2; mt++)
#pragma unroll
        for (int nt = 0; nt < 4; nt++) {
            int tok0 = wm * 32 + mt * 16 + qr;
            int j0 = wn * 32 + nt * 8 + 2 * qc;
            float4 c = acc[mt][nt];
            Cst[j0 * 130 + tok0] = c.x;
            Cst[(j0 + 1) * 130 + tok0] = c.y;
            Cst[j0 * 130 + tok0 + 8] = c.z;
            Cst[(j0 + 1) * 130 + tok0 + 8] = c.w;
        }
    __syncthreads();
    // epilogue: bias + forcing + noise -> g_u (8 token-groups of 16)
    int e = t & 63, tg = t >> 6;
    int ai_ = bt * 64 + e;
    float fr = g_fr[ai_], fi_ = g_fi[ai_], sq = g_sq[bt];
    float sbrv = sbr[e], sbiv = sbi[e];
    for (int k = 0; k < 16; k++) {
        int tk = tg * 16 + k;
        int n = b * 4096 + hw0 + tk;
        size_t ub = ((size_t)n * 16 + tt) * 128;
        float ur = Cst[e * 130 + tk] + sbrv;
        float ui = Cst[(e + 64) * 130 + tk] + sbiv;
        size_t nb = ((size_t)n * 16 + tt) * 64 + e;
        g_u[ub + e]      = ur * fr - ui * fi_ + sq * nzr[nb];
        g_u[ub + 64 + e] = ur * fi_ + ui * fr + sq * nzi[nb];
    }
}

// ---------------- K3b: in-place 16-step scan over g_u ----------------
__global__ void k_scan() {
    int t = threadIdx.x;
    int e = t & 63;
    int n = blockIdx.x * 4 + (t >> 6);
    int b = n >> 12;
    float hr = 0.f, hi = 0.f;
    for (int tt = 0; tt < 16; tt++) {
        size_t base = ((size_t)n * 16 + tt) * 128;
        float ur = g_u[base + e], ui = g_u[base + 64 + e];
        int ai_ = (b * 16 + tt) * 64 + e;
        float ar = g_ar[ai_], aiv = g_ai[ai_];
        float nhr = ar * hr - aiv * hi + ur;
        float nhi = ar * hi + aiv * hr + ui;
        hr = nhr; hi = nhi;
        g_u[base + e] = hr; g_u[base + 64 + e] = hi;
    }
}

// ---------------- K3c: decode GEMM + residual -> d_out (scalar, proven) ----------------
__global__ void k_dec(const float* __restrict__ decr, const float* __restrict__ deci,
                      float* __restrict__ out) {
    __shared__ float A[32][65];
    __shared__ float4 w4[32][16];
    __shared__ float sdr[64][65];
    int t = threadIdx.x;
    int t0 = blockIdx.x * 64;
    int bt = t0 >> 12, hw0 = t0 & 4095;
    int b = bt >> 4, tt = bt & 15;
    int token = t & 63, cg = t >> 6;
    float4 acc[4];
    for (int q = 0; q < 4; q++) acc[q] = make_float4(0, 0, 0, 0);
    for (int kc = 0; kc < 4; kc++) {
        int ci0 = kc * 32;
        __syncthreads();
        for (int r = 0; r < 8; r++) {
            int idx = t + 256 * r;
            int kk = idx & 31, tl = idx >> 5;
            A[kk][tl] = g_u[((size_t)(b * 4096 + hw0 + tl) * 16 + tt) * 128 + ci0 + kk];
        }
        for (int r = 0; r < 2; r++) {
            int idx = t + 256 * r;
            int kk = idx >> 4, j4 = idx & 15;
            int k = ci0 + kk;
            float4 v = (k < 64) ? ld4(decr + k * 64 + j4 * 4)
                                : neg4(ld4(deci + (k - 64) * 64 + j4 * 4));
            w4[kk][j4] = v;
        }
        __syncthreads();
#pragma unroll 8
        for (int kk = 0; kk < 32; kk++) {
            float tv = A[kk][token];
#pragma unroll
            for (int q = 0; q < 4; q++) fma4(acc[q], tv, w4[kk][cg * 4 + q]);
        }
    }
    __syncthreads();
    for (int q = 0; q < 4; q++)
        for (int m = 0; m < 4; m++) {
            int d = cg * 16 + q * 4 + m;
            sdr[d][token] = ((const float*)&acc[q])[m];
        }
    __syncthreads();
    int tk = t & 63, d0 = t >> 6;
    for (int k = 0; k < 16; k++) {
        int d = d0 + 4 * k;
        size_t gi = ((size_t)(bt * 64 + d)) * 4096 + hw0 + tk;
        out[gi] = g_x1r[gi] + sdr[d][tk];
        out[IMOFF + gi] = g_x1i[gi];
    }
}

// ---------------- K4: fused MoE with tf32 mma (512 thr) ----------------
// block = 128 tokens x 128 outputs; 16 warps wm(4) x wn(4), 32tok x 32j per warp.
#define MOE_ASTR 132
#define MOE_BSTR 136
__global__ __launch_bounds__(512, 1) void k_moe(
        const float* __restrict__ rw, const float* __restrict__ rb,
        const float* __restrict__ w1, const float* __restrict__ b1,
        const float* __restrict__ w2, const float* __restrict__ b2,
        float* __restrict__ out) {
    extern __shared__ uint32_t ms[];
    uint32_t* A  = ms;                         // [128][132] tokens (tf32)
    uint32_t* HS = ms + 128 * MOE_ASTR;        // [128][132] hidden (tf32); reused as C stage
    uint32_t* B  = ms + 2 * 128 * MOE_ASTR;    // [32][136]
    float* G     = (float*)(ms + 2 * 128 * MOE_ASTR + 32 * MOE_BSTR);  // [4][128]
    float* Cst   = (float*)HS;                 // [128 o][130]
    int t = threadIdx.x;
    int t0 = blockIdx.x * 128;
    int bt = t0 >> 12, hw0 = t0 & 4095;
    int wrp = t >> 5, lane = t & 31;
    int wm = wrp & 3, wn = wrp >> 2;
    int qr = lane >> 2, qc = lane & 3;

    for (int r = 0; r < 32; r++) {
        int idx = t + 512 * r;
        int c = idx >> 7, tl = idx & 127;
        float v = (c < 64) ? out[((size_t)(bt * 64 + c)) * 4096 + hw0 + tl]
                           : out[IMOFF + ((size_t)(bt * 64 + c - 64)) * 4096 + hw0 + tl];
        A[tl * MOE_ASTR + c] = f2tf32(v);
    }
    __syncthreads();
    if (t < 128) {
        float l0 = rb[0], l1 = rb[1], l2 = rb[2], l3 = rb[3];
        for (int c = 0; c < 128; c++) {
            float v = __uint_as_float(A[t * MOE_ASTR + c]);
            float4 wv = ld4(rw + c * 4);
            l0 = fmaf(v, wv.x, l0); l1 = fmaf(v, wv.y, l1);
            l2 = fmaf(v, wv.z, l2); l3 = fmaf(v, wv.w, l3);
        }
        float m = fmaxf(fmaxf(l0, l1), fmaxf(l2, l3));
        float e0 = expf(l0 - m), e1 = expf(l1 - m), e2 = expf(l2 - m), e3 = expf(l3 - m);
        float inv = 1.f / (e0 + e1 + e2 + e3);
        G[0 * 128 + t] = e0 * inv; G[1 * 128 + t] = e1 * inv;
        G[2 * 128 + t] = e2 * inv; G[3 * 128 + t] = e3 * inv;
    }
    float4 acc2[2][4];
#pragma unroll
    for (int i = 0; i < 2; i++)
#pragma unroll
        for (int j = 0; j < 4; j++) acc2[i][j] = make_float4(0, 0, 0, 0);

    for (int e = 0; e < 4; e++) {
        float4 acc1[2][4];
#pragma unroll
        for (int i = 0; i < 2; i++)
#pragma unroll
            for (int j = 0; j < 4; j++) acc1[i][j] = make_float4(0, 0, 0, 0);
        // GEMM1: A @ w1[e]
        for (int kc = 0; kc < 4; kc++) {
            int ci0 = kc * 32;
            __syncthreads();
            for (int idx = t; idx < 4096; idx += 512) {
                int kk = idx >> 7, j = idx & 127;
                B[kk * MOE_BSTR + j] = f2tf32(w1[(size_t)e * 16384 + (ci0 + kk) * 128 + j]);
            }
            __syncthreads();
#pragma unroll
            for (int ks = 0; ks < 4; ks++) {
                int acol = ci0 + ks * 8 + qc;
                uint32_t af[2][4];
#pragma unroll
                for (int mt = 0; mt < 2; mt++) {
                    int base = (wm * 32 + mt * 16) * MOE_ASTR;
                    af[mt][0] = A[base + qr * MOE_ASTR + acol];
                    af[mt][1] = A[base + (qr + 8) * MOE_ASTR + acol];
                    af[mt][2] = A[base + qr * MOE_ASTR + acol + 4];
                    af[mt][3] = A[base + (qr + 8) * MOE_ASTR + acol + 4];
                }
                int br0 = (ks * 8 + qc) * MOE_BSTR, br1 = br0 + 4 * MOE_BSTR;
#pragma unroll
                for (int nt = 0; nt < 4; nt++) {
                    int j = wn * 32 + nt * 8 + qr;
                    uint32_t b0 = B[br0 + j], b1v = B[br1 + j];
                    mma_tf32(acc1[0][nt], af[0][0], af[0][1], af[0][2], af[0][3], b0, b1v);
                    mma_tf32(acc1[1][nt], af[1][0], af[1][1], af[1][2], af[1][3], b0, b1v);
                }
            }
        }
        __syncthreads();
        // epilogue1: bias + gelu * gate -> HS (rna tf32)
#pragma unroll
        for (int mt = 0; mt < 2; mt++)
#pragma unroll
            for (int nt = 0; nt < 4; nt++) {
                int tok0 = wm * 32 + mt * 16 + qr;
                int j0 = wn * 32 + nt * 8 + 2 * qc;
                float4 c = acc1[mt][nt];
                float b1v0 = b1[e * 128 + j0], b1v1 = b1[e * 128 + j0 + 1];
                float g0 = G[e * 128 + tok0], g8 = G[e * 128 + tok0 + 8];
                HS[tok0 * MOE_ASTR + j0]           = f2tf32(gelu_tanh(c.x + b1v0) * g0);
                HS[tok0 * MOE_ASTR + j0 + 1]       = f2tf32(gelu_tanh(c.y + b1v1) * g0);
                HS[(tok0 + 8) * MOE_ASTR + j0]     = f2tf32(gelu_tanh(c.z + b1v0) * g8);
                HS[(tok0 + 8) * MOE_ASTR + j0 + 1] = f2tf32(gelu_tanh(c.w + b1v1) * g8);
            }
        // GEMM2: HS @ w2[e] -> acc2
        for (int kc = 0; kc < 4; kc++) {
            int ci0 = kc * 32;
            __syncthreads();
            for (int idx = t; idx < 4096; idx += 512) {
                int kk = idx >> 7, j = idx & 127;
                B[kk * MOE_BSTR + j] = f2tf32(w2[(size_t)e * 16384 + (ci0 + kk) * 128 + j]);
            }
            __syncthreads();
#pragma unroll
            for (int ks = 0; ks < 4; ks++) {
                int acol = ci0 + ks * 8 + qc;
                uint32_t af[2][4];
#pragma unroll
                for (int mt = 0; mt < 2; mt++) {
                    int base = (wm * 32 + mt * 16) * MOE_ASTR;
                    af[mt][0] = HS[base + qr * MOE_ASTR + acol];
                    af[mt][1] = HS[base + (qr + 8) * MOE_ASTR + acol];
                    af[mt][2] = HS[base + qr * MOE_ASTR + acol + 4];
                    af[mt][3] = HS[base + (qr + 8) * MOE_ASTR + acol + 4];
                }
                int br0 = (ks * 8 + qc) * MOE_BSTR, br1 = br0 + 4 * MOE_BSTR;
#pragma unroll
                for (int nt = 0; nt < 4; nt++) {
                    int j = wn * 32 + nt * 8 + qr;
                    uint32_t b0 = B[br0 + j], b1v = B[br1 + j];
                    mma_tf32(acc2[0][nt], af[0][0], af[0][1], af[0][2], af[0][3], b0, b1v);
                    mma_tf32(acc2[1][nt], af[1][0], af[1][1], af[1][2], af[1][3], b0, b1v);
                }
            }
        }
        __syncthreads();
    }
#pragma unroll
    for (int mt = 0; mt < 2; mt++)
#pragma unroll
        for (int nt = 0; nt < 4; nt++) {
            int tok0 = wm * 32 + mt * 16 + qr;
            int o0 = wn * 32 + nt * 8 + 2 * qc;
            float4 c = acc2[mt][nt];
            Cst[o0 * 130 + tok0] = c.x;
            Cst[(o0 + 1) * 130 + tok0] = c.y;
            Cst[o0 * 130 + tok0 + 8] = c.z;
            Cst[(o0 + 1) * 130 + tok0 + 8] = c.w;
        }
    __syncthreads();
    int tl = t & 127, og = t >> 7;
    float g0 = G[tl], g1 = G[128 + tl], g2 = G[256 + tl], g3 = G[384 + tl];
    for (int j = 0; j < 32; j++) {
        int o = og * 32 + j;
        float delta = Cst[o * 130 + tl] +
                      g0 * b2[o] + g1 * b2[128 + o] + g2 * b2[256 + o] + g3 * b2[384 + o];
        size_t gi = (o < 64) ? ((size_t)(bt * 64 + o)) * 4096 + hw0 + tl
                             : IMOFF + ((size_t)(bt * 64 + o - 64)) * 4096 + hw0 + tl;
        out[gi] += delta;
    }
}

extern "C" void kernel_launch(void* const* d_in, const int* in_sizes, int n_in,
                              void* d_out, int out_size) {
    const float* x_real = (const float*)d_in[0];
    const float* x_imag = (const float*)d_in[1];
    const float* dt     = (const float*)d_in[2];
    const float* nz_r   = (const float*)d_in[3];
    const float* nz_i   = (const float*)d_in[4];
    const float* ln_s_w = (const float*)d_in[5];
    const float* ln_s_b = (const float*)d_in[6];
    const float* conv_w = (const float*)d_in[7];
    const float* conv_b = (const float*)d_in[8];
    const float* ln_t_w = (const float*)d_in[9];
    const float* ln_t_b = (const float*)d_in[10];
    const float* lam_re = (const float*)d_in[11];
    const float* lam_im = (const float*)d_in[12];
    const float* sb_re  = (const float*)d_in[13];
    const float* sb_im  = (const float*)d_in[14];
    const float* enc_re = (const float*)d_in[15];
    const float* enc_im = (const float*)d_in[16];
    const float* dec_re = (const float*)d_in[17];
    const float* dec_im = (const float*)d_in[18];
    const float* rw     = (const float*)d_in[19];
    const float* rb     = (const float*)d_in[20];
    const float* w1     = (const float*)d_in[21];
    const float* b1     = (const float*)d_in[22];
    const float* w2     = (const float*)d_in[23];
    const float* b2     = (const float*)d_in[24];
    float* out = (float*)d_out;

    int conv_smem = 128 * 130 * 4;                                     // 66560 B
    int enc_smem  = (128 * ENC_ASTR + 128 * ENC_BSTR + 256) * 4;       // 138240 B
    int moe_smem  = (2 * 128 * MOE_ASTR + 32 * MOE_BSTR + 512) * 4;    // 154624 B
    cudaFuncSetAttribute(k_conv, cudaFuncAttributeMaxDynamicSharedMemorySize, conv_smem);
    cudaFuncSetAttribute(k_enc, cudaFuncAttributeMaxDynamicSharedMemorySize, enc_smem);
    cudaFuncSetAttribute(k_moe, cudaFuncAttributeMaxDynamicSharedMemorySize, moe_smem);

    k_setup<<<8, 256>>>(dt, lam_re, lam_im);
    k_sln<<<2048, 256>>>(x_real, x_imag, ln_s_w, ln_s_b);
    k_conv<<<dim3(32, 32), 256, conv_smem>>>(conv_w, conv_b, x_real, x_imag);
    k_enc<<<1024, 512, enc_smem>>>(ln_t_w, ln_t_b, enc_re, enc_im, sb_re, sb_im, nz_r, nz_i);
    k_scan<<<2048, 256>>>();
    k_dec<<<2048, 256>>>(dec_re, dec_im, out);
    k_moe<<<1024, 512, moe_smem>>>(rw, rb, w1, b1, w2, b2, out);
}

// round 7
// speedup vs baseline: 1.5607x; 1.0597x over previous
#include <cuda_runtime.h>
#include <math.h>
#include <stdint.h>

#define BT 32
#define DIM 64
#define HW 4096
#define N2 131072
#define IMOFF 8388608
#define LNEPS 1e-5f

// ---------------- scratch ----------------
__device__ __align__(16) float g_xc[(size_t)BT * HW * 128];   // LN'd conv input (pixel-major, tf32-rounded)
__device__ __align__(16) float g_x1r[(size_t)BT * DIM * HW];
__device__ __align__(16) float g_x1i[(size_t)BT * DIM * HW];
__device__ __align__(16) float g_u[(size_t)8192 * 16 * 128];  // u then h in-place, [n][t][128]
__device__ float g_ar[BT * DIM], g_ai[BT * DIM], g_fr[BT * DIM], g_fi[BT * DIM], g_sq[BT];

__device__ __forceinline__ float gelu_tanh(float x) {
    float t = 0.7978845608028654f * (x + 0.044715f * x * x * x);
    return 0.5f * x * (1.0f + tanhf(t));
}
__device__ __forceinline__ float4 ld4(const float* p) { return *(const float4*)p; }
__device__ __forceinline__ uint32_t f2tf32(float f) {
    uint32_t u; asm("cvt.rna.tf32.f32 %0, %1;" : "=r"(u) : "f"(f)); return u;
}
__device__ __forceinline__ void mma_tf32(float4& c, uint32_t a0, uint32_t a1, uint32_t a2,
                                         uint32_t a3, uint32_t b0, uint32_t b1) {
    asm volatile("mma.sync.aligned.m16n8k8.row.col.f32.tf32.tf32.f32 "
                 "{%0,%1,%2,%3}, {%4,%5,%6,%7}, {%8,%9}, {%0,%1,%2,%3};"
                 : "+f"(c.x), "+f"(c.y), "+f"(c.z), "+f"(c.w)
                 : "r"(a0), "r"(a1), "r"(a2), "r"(a3), "r"(b0), "r"(b1));
}

// ---------------- K0: per-(b,t,d) decay & forcing ----------------
__global__ void k_setup(const float* __restrict__ dt, const float* __restrict__ lam_re,
                        const float* __restrict__ lam_im) {
    int i = blockIdx.x * blockDim.x + threadIdx.x;
    if (i >= BT * DIM) return;
    int bt = i >> 6, d = i & 63;
    float dtv = dt[bt];
    float x = lam_re[d];
    float sp = (x > 20.f) ? x : log1pf(expf(x));
    float lr = -sp, li = lam_im[d];
    float er = expf(lr * dtv);
    float ar = er * cosf(li * dtv), ai = er * sinf(li * dtv);
    float den = lr * lr + li * li;
    g_ar[i] = ar; g_ai[i] = ai;
    g_fr[i] = ((ar - 1.f) * lr + ai * li) / den;
    g_fi[i] = (ai * lr - (ar - 1.f) * li) / den;
    if (d == 0) g_sq[bt] = 0.01f * sqrtf(dtv);
}

// ---------------- K1: spatial complex LayerNorm -> g_xc (tf32-rounded) ----------------
__global__ void k_sln(const float* __restrict__ xr, const float* __restrict__ xi,
                      const float* __restrict__ w, const float* __restrict__ b) {
    __shared__ float sh[128][65];
    __shared__ float smu[64], srs[64];
    int t = threadIdx.x;
    int p0 = blockIdx.x * 64;
    int bt = p0 >> 12, hw0 = p0 & 4095;
    for (int r = 0; r < 32; r++) {
        int idx = t + 256 * r;
        int c = idx >> 6, p = idx & 63;
        float v = (c < 64) ? xr[((size_t)(bt * 64 + c)) * 4096 + hw0 + p]
                           : xi[((size_t)(bt * 64 + c - 64)) * 4096 + hw0 + p];
        sh[c][p] = v;
    }
    __syncthreads();
    int wid = t >> 5, lane = t & 31;
    if (wid < 8) {
        for (int pp = 0; pp < 8; pp++) {
            int p = wid * 8 + pp;
            float s = 0.f, s2 = 0.f;
            for (int cc = lane; cc < 128; cc += 32) {
                float v = sh[cc][p]; s += v; s2 += v * v;
            }
            for (int o = 16; o; o >>= 1) {
                s += __shfl_xor_sync(0xffffffffu, s, o);
                s2 += __shfl_xor_sync(0xffffffffu, s2, o);
            }
            if (lane == 0) {
                float mu = s * (1.f / 128.f);
                smu[p] = mu;
                srs[p] = rsqrtf(s2 * (1.f / 128.f) - mu * mu + LNEPS);
            }
        }
    }
    __syncthreads();
    for (int r = 0; r < 32; r++) {
        int idx = t + 256 * r;
        int p = idx >> 7, c = idx & 127;
        float v = (sh[c][p] - smu[p]) * srs[p] * w[c] + b[c];
        g_xc[((size_t)(p0 + p)) * 128 + c] = __uint_as_float(f2tf32(v));
    }
}

// ---------------- K2: 3x3 conv via tf32 mma, + bias + residual -> x1 ----------------
#define CONV_ASTR 36
#define CONV_BSTR 136
__global__ void k_conv(const float* __restrict__ cw, const float* __restrict__ cb,
                       const float* __restrict__ xr, const float* __restrict__ xi) {
    extern __shared__ uint32_t cs[];
    uint32_t* A = cs;                  // [264][36]
    uint32_t* B = cs + 264 * CONV_ASTR;// [32][136]
    float* Cst = (float*)cs;           // epilogue stage [128 co][130]
    int t = threadIdx.x;
    int h0 = blockIdx.x * 2, bt = blockIdx.y;
    int wrp = t >> 5, lane = t & 31;
    int wm = wrp & 3, wn = wrp >> 2;
    int qr = lane >> 2, qc = lane & 3;
    float4 acc[2][8];
#pragma unroll
    for (int i = 0; i < 2; i++)
#pragma unroll
        for (int j = 0; j < 8; j++) acc[i][j] = make_float4(0, 0, 0, 0);

    for (int kc = 0; kc < 4; kc++) {
        int ci0 = kc * 32;
        __syncthreads();
        for (int r = 0; r < 4; r++) {
            int gh = h0 + r - 1;
            for (int idx = t; idx < 2112; idx += 256) {
                int xx = idx >> 5, c = idx & 31;
                int gw = xx - 1;
                float v = 0.f;
                if ((unsigned)gh < 64u && (unsigned)gw < 64u)
                    v = g_xc[((size_t)(bt * 4096 + gh * 64 + gw)) * 128 + ci0 + c];
                A[(r * 66 + xx) * CONV_ASTR + c] = __float_as_uint(v);
            }
        }
        for (int tap = 0; tap < 9; tap++) {
            int dy = tap / 3 - 1, dx = tap % 3 - 1;
            __syncthreads();
            for (int idx = t; idx < 4096; idx += 256) {
                int kk = idx >> 7, co = idx & 127;
                B[kk * CONV_BSTR + co] = f2tf32(cw[((size_t)(tap * 128 + ci0 + kk)) * 128 + co]);
            }
            __syncthreads();
            int prs[4];
#pragma unroll
            for (int i = 0; i < 4; i++) {
                int m = wm * 32 + i * 8 + qr;
                int y = m >> 6, x = m & 63;
                prs[i] = (y + dy + 1) * 66 + (x + dx + 1);
            }
#pragma unroll
            for (int ks = 0; ks < 4; ks++) {
                int acol = ks * 8 + qc;
                uint32_t af[4][2];
#pragma unroll
                for (int i = 0; i < 4; i++) {
                    af[i][0] = A[prs[i] * CONV_ASTR + acol];
                    af[i][1] = A[prs[i] * CONV_ASTR + acol + 4];
                }
                int brow0 = (ks * 8 + qc) * CONV_BSTR;
                int brow1 = brow0 + 4 * CONV_BSTR;
#pragma unroll
                for (int nt = 0; nt < 8; nt++) {
                    int co = wn * 64 + nt * 8 + qr;
                    uint32_t b0 = B[brow0 + co], b1 = B[brow1 + co];
                    mma_tf32(acc[0][nt], af[0][0], af[1][0], af[0][1], af[1][1], b0, b1);
                    mma_tf32(acc[1][nt], af[2][0], af[3][0], af[2][1], af[3][1], b0, b1);
                }
            }
        }
    }
    __syncthreads();
#pragma unroll
    for (int mt = 0; mt < 2; mt++)
#pragma unroll
        for (int nt = 0; nt < 8; nt++) {
            int m0 = wm * 32 + mt * 16 + qr;
            int n0 = wn * 64 + nt * 8 + 2 * qc;
            float4 c = acc[mt][nt];
            Cst[n0 * 130 + m0] = c.x;
            Cst[(n0 + 1) * 130 + m0] = c.y;
            Cst[n0 * 130 + m0 + 8] = c.z;
            Cst[(n0 + 1) * 130 + m0 + 8] = c.w;
        }
    __syncthreads();
    int p = t & 127, og = t >> 7;
    size_t pb = (size_t)h0 * 64 + p;
    for (int j = 0; j < 64; j++) {
        int co = og * 64 + j;
        float v = Cst[co * 130 + p] + cb[co];
        if (co < 64) {
            size_t gi = ((size_t)(bt * 64 + co)) * 4096 + pb;
            g_x1r[gi] = v + xr[gi];
        } else {
            size_t gi = ((size_t)(bt * 64 + co - 64)) * 4096 + pb;
            g_x1i[gi] = v + xi[gi];
        }
    }
}

// ---------------- K3a: temporal LN + encode (tf32 mma, 512 thr) -> g_u ----------------
#define ENC_ASTR 132
#define ENC_BSTR 136
__global__ __launch_bounds__(512, 1) void k_enc(
        const float* __restrict__ ltw, const float* __restrict__ ltb,
        const float* __restrict__ encr, const float* __restrict__ enci,
        const float* __restrict__ sbr, const float* __restrict__ sbi,
        const float* __restrict__ nzr, const float* __restrict__ nzi) {
    extern __shared__ uint32_t es[];
    uint32_t* A = es;                        // [128 tok][132 k]
    uint32_t* B = es + 128 * ENC_ASTR;       // [128 k][136 j] tf32
    float* smu = (float*)(es + 128 * ENC_ASTR + 128 * ENC_BSTR);
    float* srs = smu + 128;
    float* Af = (float*)A;
    float* Cst = (float*)A;
    int t = threadIdx.x;
    int t0 = blockIdx.x * 128;
    int bt = t0 >> 12, hw0 = t0 & 4095;
    int b = bt >> 4, tt = bt & 15;
    int wrp = t >> 5, lane = t & 31;
    int wm = wrp & 3, wn = wrp >> 2;
    int qr = lane >> 2, qc = lane & 3;

    for (int r = 0; r < 32; r++) {
        int idx = t + 512 * r;
        int c = idx >> 7, tl = idx & 127;
        float v = (c < 64) ? g_x1r[((size_t)(bt * 64 + c)) * 4096 + hw0 + tl]
                           : g_x1i[((size_t)(bt * 64 + c - 64)) * 4096 + hw0 + tl];
        Af[tl * ENC_ASTR + c] = v;
    }
    for (int r = 0; r < 32; r++) {
        int idx = t + 512 * r;
        int k = idx >> 7, j = idx & 127;
        float v;
        if (k < 64) v = (j < 64) ? encr[k * 64 + j] : enci[k * 64 + (j - 64)];
        else        v = (j < 64) ? -enci[(k - 64) * 64 + j] : encr[(k - 64) * 64 + (j - 64)];
        B[k * ENC_BSTR + j] = f2tf32(v);
    }
    __syncthreads();
    for (int sub = 0; sub < 8; sub++) {
        int tok = wrp * 8 + sub;
        float s = 0.f, s2 = 0.f;
        for (int k = lane; k < 128; k += 32) {
            float v = Af[tok * ENC_ASTR + k]; s += v; s2 += v * v;
        }
        for (int o = 16; o; o >>= 1) {
            s += __shfl_xor_sync(0xffffffffu, s, o);
            s2 += __shfl_xor_sync(0xffffffffu, s2, o);
        }
        if (lane == 0) {
            float mu = s * (1.f / 128.f);
            smu[tok] = mu;
            srs[tok] = rsqrtf(s2 * (1.f / 128.f) - mu * mu + LNEPS);
        }
    }
    __syncthreads();
    for (int r = 0; r < 32; r++) {
        int idx = t + 512 * r;
        int tok = idx >> 7, k = idx & 127;
        float v = (Af[tok * ENC_ASTR + k] - smu[tok]) * srs[tok] * ltw[k] + ltb[k];
        A[tok * ENC_ASTR + k] = f2tf32(v);
    }
    __syncthreads();
    float4 acc[2][4];
#pragma unroll
    for (int i = 0; i < 2; i++)
#pragma unroll
        for (int j = 0; j < 4; j++) acc[i][j] = make_float4(0, 0, 0, 0);
#pragma unroll
    for (int ks = 0; ks < 16; ks++) {
        int acol = ks * 8 + qc;
        uint32_t af[2][4];
#pragma unroll
        for (int mt = 0; mt < 2; mt++) {
            int base = (wm * 32 + mt * 16) * ENC_ASTR;
            af[mt][0] = A[base + qr * ENC_ASTR + acol];
            af[mt][1] = A[base + (qr + 8) * ENC_ASTR + acol];
            af[mt][2] = A[base + qr * ENC_ASTR + acol + 4];
            af[mt][3] = A[base + (qr + 8) * ENC_ASTR + acol + 4];
        }
        int br0 = (ks * 8 + qc) * ENC_BSTR, br1 = br0 + 4 * ENC_BSTR;
#pragma unroll
        for (int nt = 0; nt < 4; nt++) {
            int j = wn * 32 + nt * 8 + qr;
            uint32_t b0 = B[br0 + j], b1 = B[br1 + j];
            mma_tf32(acc[0][nt], af[0][0], af[0][1], af[0][2], af[0][3], b0, b1);
            mma_tf32(acc[1][nt], af[1][0], af[1][1], af[1][2], af[1][3], b0, b1);
        }
    }
    __syncthreads();
#pragma unroll
    for (int mt = 0; mt < 2; mt++)
#pragma unroll
        for (int nt = 0; nt < 4; nt++) {
            int tok0 = wm * 32 + mt * 16 + qr;
            int j0 = wn * 32 + nt * 8 + 2 * qc;
            float4 c = acc[mt][nt];
            Cst[j0 * 130 + tok0] = c.x;
            Cst[(j0 + 1) * 130 + tok0] = c.y;
            Cst[j0 * 130 + tok0 + 8] = c.z;
            Cst[(j0 + 1) * 130 + tok0 + 8] = c.w;
        }
    __syncthreads();
    int e = t & 63, tg = t >> 6;
    int ai_ = bt * 64 + e;
    float fr = g_fr[ai_], fi_ = g_fi[ai_], sq = g_sq[bt];
    float sbrv = sbr[e], sbiv = sbi[e];
    for (int k = 0; k < 16; k++) {
        int tk = tg * 16 + k;
        int n = b * 4096 + hw0 + tk;
        size_t ub = ((size_t)n * 16 + tt) * 128;
        float ur = Cst[e * 130 + tk] + sbrv;
        float ui = Cst[(e + 64) * 130 + tk] + sbiv;
        size_t nb = ((size_t)n * 16 + tt) * 64 + e;
        g_u[ub + e]      = ur * fr - ui * fi_ + sq * nzr[nb];
        g_u[ub + 64 + e] = ur * fi_ + ui * fr + sq * nzi[nb];
    }
}

// ---------------- K3b: in-place 16-step scan over g_u ----------------
__global__ void k_scan() {
    int t = threadIdx.x;
    int e = t & 63;
    int n = blockIdx.x * 4 + (t >> 6);
    int b = n >> 12;
    float hr = 0.f, hi = 0.f;
    for (int tt = 0; tt < 16; tt++) {
        size_t base = ((size_t)n * 16 + tt) * 128;
        float ur = g_u[base + e], ui = g_u[base + 64 + e];
        int ai_ = (b * 16 + tt) * 64 + e;
        float ar = g_ar[ai_], aiv = g_ai[ai_];
        float nhr = ar * hr - aiv * hi + ur;
        float nhi = ar * hi + aiv * hr + ui;
        hr = nhr; hi = nhi;
        g_u[base + e] = hr; g_u[base + 64 + e] = hi;
    }
}

// ---------------- K4: fused decode + residual + MoE -> d_out (512 thr) ----------------
// smem: AU [128][132] (h -> HS -> Cst), TOK [128][132], DR [64][130], B [32][136], G [4][128]
#define DO_ASTR 132
#define DO_BSTR 136
__global__ __launch_bounds__(512, 1) void k_out(
        const float* __restrict__ decr, const float* __restrict__ deci,
        const float* __restrict__ rw, const float* __restrict__ rb,
        const float* __restrict__ w1, const float* __restrict__ b1,
        const float* __restrict__ w2, const float* __restrict__ b2,
        float* __restrict__ out) {
    extern __shared__ uint32_t os[];
    uint32_t* AU  = os;                    // 16896 words
    uint32_t* TOK = os + 16896;            // 16896 words
    float* DRf    = (float*)(os + 33792);  // 8320 words [64 d][130]
    uint32_t* B   = os + 42112;            // 4352 words
    float* G      = (float*)(os + 46464);  // 512 words
    float* Bf = (float*)B;
    float* Cst = (float*)AU;
    float* TOKf = (float*)TOK;
    int t = threadIdx.x;
    int t0 = blockIdx.x * 128;
    int bt = t0 >> 12, hw0 = t0 & 4095;
    int b = bt >> 4, tt = bt & 15;
    int wrp = t >> 5, lane = t & 31;
    int wm = wrp & 3, wn = wrp >> 2;
    int qr = lane >> 2, qc = lane & 3;

    // 1. load h tile -> AU (rna tf32), coalesced rows
    for (int r = 0; r < 32; r++) {
        int idx = t + 512 * r;
        int tok = idx >> 7, k = idx & 127;
        float v = g_u[((size_t)(b * 4096 + hw0 + tok) * 16 + tt) * 128 + k];
        AU[tok * DO_ASTR + k] = f2tf32(v);
    }
    // 2+3. dec mma over 4 k-chunks; B chunk [32 k][64 d] stride 72
    float4 dacc[2][2];
#pragma unroll
    for (int i = 0; i < 2; i++)
#pragma unroll
        for (int j = 0; j < 2; j++) dacc[i][j] = make_float4(0, 0, 0, 0);
    for (int kc = 0; kc < 4; kc++) {
        int k0 = kc * 32;
        __syncthreads();
        for (int r = 0; r < 4; r++) {
            int idx = t + 512 * r;
            int kk = idx >> 6, d = idx & 63;
            int k = k0 + kk;
            float v = (k < 64) ? decr[k * 64 + d] : -deci[(k - 64) * 64 + d];
            B[kk * 72 + d] = f2tf32(v);
        }
        __syncthreads();
#pragma unroll
        for (int ks = 0; ks < 4; ks++) {
            int acol = k0 + ks * 8 + qc;
            uint32_t af[2][4];
#pragma unroll
            for (int mt = 0; mt < 2; mt++) {
                int base = (wm * 32 + mt * 16) * DO_ASTR;
                af[mt][0] = AU[base + qr * DO_ASTR + acol];
                af[mt][1] = AU[base + (qr + 8) * DO_ASTR + acol];
                af[mt][2] = AU[base + qr * DO_ASTR + acol + 4];
                af[mt][3] = AU[base + (qr + 8) * DO_ASTR + acol + 4];
            }
            int br0 = (ks * 8 + qc) * 72, br1 = br0 + 4 * 72;
#pragma unroll
            for (int nt = 0; nt < 2; nt++) {
                int j = wn * 16 + nt * 8 + qr;
                uint32_t b0 = B[br0 + j], b1v = B[br1 + j];
                mma_tf32(dacc[0][nt], af[0][0], af[0][1], af[0][2], af[0][3], b0, b1v);
                mma_tf32(dacc[1][nt], af[1][0], af[1][1], af[1][2], af[1][3], b0, b1v);
            }
        }
    }
    __syncthreads();
    // stage drift -> DR[d][tok]
#pragma unroll
    for (int mt = 0; mt < 2; mt++)
#pragma unroll
        for (int nt = 0; nt < 2; nt++) {
            int tok0 = wm * 32 + mt * 16 + qr;
            int d0 = wn * 16 + nt * 8 + 2 * qc;
            float4 c = dacc[mt][nt];
            DRf[d0 * 130 + tok0] = c.x;
            DRf[(d0 + 1) * 130 + tok0] = c.y;
            DRf[d0 * 130 + tok0 + 8] = c.z;
            DRf[(d0 + 1) * 130 + tok0 + 8] = c.w;
        }
    __syncthreads();
    // 4. build tokens (rna tf32): real = x1r + drift, imag = x1i
    for (int r = 0; r < 32; r++) {
        int idx = t + 512 * r;
        int c = idx >> 7, tl = idx & 127;
        float v;
        if (c < 64) v = g_x1r[((size_t)(bt * 64 + c)) * 4096 + hw0 + tl] + DRf[c * 130 + tl];
        else        v = g_x1i[((size_t)(bt * 64 + c - 64)) * 4096 + hw0 + tl];
        TOK[tl * DO_ASTR + c] = f2tf32(v);
    }
    __syncthreads();
    // 5. gates: 512 threads = (token, expert) logits, then softmax by 128
    {
        int tok = t & 127, e = t >> 7;
        float l = rb[e];
        for (int c = 0; c < 128; c++)
            l = fmaf(TOKf[tok * DO_ASTR + c], rw[c * 4 + e], l);
        G[e * 128 + tok] = l;
    }
    __syncthreads();
    if (t < 128) {
        float l0 = G[t], l1 = G[128 + t], l2 = G[256 + t], l3 = G[384 + t];
        float m = fmaxf(fmaxf(l0, l1), fmaxf(l2, l3));
        float e0 = expf(l0 - m), e1 = expf(l1 - m), e2 = expf(l2 - m), e3 = expf(l3 - m);
        float inv = 1.f / (e0 + e1 + e2 + e3);
        G[t] = e0 * inv; G[128 + t] = e1 * inv;
        G[256 + t] = e2 * inv; G[384 + t] = e3 * inv;
    }
    __syncthreads();
    // 6. MoE over 4 experts
    float4 acc2[2][4];
#pragma unroll
    for (int i = 0; i < 2; i++)
#pragma unroll
        for (int j = 0; j < 4; j++) acc2[i][j] = make_float4(0, 0, 0, 0);

    for (int e = 0; e < 4; e++) {
        float4 acc1[2][4];
#pragma unroll
        for (int i = 0; i < 2; i++)
#pragma unroll
            for (int j = 0; j < 4; j++) acc1[i][j] = make_float4(0, 0, 0, 0);
        // GEMM1: TOK @ w1[e]
        for (int kc = 0; kc < 4; kc++) {
            int ci0 = kc * 32;
            __syncthreads();
            for (int idx = t; idx < 4096; idx += 512) {
                int kk = idx >> 7, j = idx & 127;
                B[kk * DO_BSTR + j] = f2tf32(w1[(size_t)e * 16384 + (ci0 + kk) * 128 + j]);
            }
            __syncthreads();
#pragma unroll
            for (int ks = 0; ks < 4; ks++) {
                int acol = ci0 + ks * 8 + qc;
                uint32_t af[2][4];
#pragma unroll
                for (int mt = 0; mt < 2; mt++) {
                    int base = (wm * 32 + mt * 16) * DO_ASTR;
                    af[mt][0] = TOK[base + qr * DO_ASTR + acol];
                    af[mt][1] = TOK[base + (qr + 8) * DO_ASTR + acol];
                    af[mt][2] = TOK[base + qr * DO_ASTR + acol + 4];
                    af[mt][3] = TOK[base + (qr + 8) * DO_ASTR + acol + 4];
                }
                int br0 = (ks * 8 + qc) * DO_BSTR, br1 = br0 + 4 * DO_BSTR;
#pragma unroll
                for (int nt = 0; nt < 4; nt++) {
                    int j = wn * 32 + nt * 8 + qr;
                    uint32_t b0 = B[br0 + j], b1v = B[br1 + j];
                    mma_tf32(acc1[0][nt], af[0][0], af[0][1], af[0][2], af[0][3], b0, b1v);
                    mma_tf32(acc1[1][nt], af[1][0], af[1][1], af[1][2], af[1][3], b0, b1v);
                }
            }
        }
        __syncthreads();
        // epilogue1: bias + gelu * gate -> HS (in AU, rna tf32)
#pragma unroll
        for (int mt = 0; mt < 2; mt++)
#pragma unroll
            for (int nt = 0; nt < 4; nt++) {
                int tok0 = wm * 32 + mt * 16 + qr;
                int j0 = wn * 32 + nt * 8 + 2 * qc;
                float4 c = acc1[mt][nt];
                float b1v0 = b1[e * 128 + j0], b1v1 = b1[e * 128 + j0 + 1];
                float g0 = G[e * 128 + tok0], g8 = G[e * 128 + tok0 + 8];
                AU[tok0 * DO_ASTR + j0]           = f2tf32(gelu_tanh(c.x + b1v0) * g0);
                AU[tok0 * DO_ASTR + j0 + 1]       = f2tf32(gelu_tanh(c.y + b1v1) * g0);
                AU[(tok0 + 8) * DO_ASTR + j0]     = f2tf32(gelu_tanh(c.z + b1v0) * g8);
                AU[(tok0 + 8) * DO_ASTR + j0 + 1] = f2tf32(gelu_tanh(c.w + b1v1) * g8);
            }
        // GEMM2: HS @ w2[e] -> acc2
        for (int kc = 0; kc < 4; kc++) {
            int ci0 = kc * 32;
            __syncthreads();
            for (int idx = t; idx < 4096; idx += 512) {
                int kk = idx >> 7, j = idx & 127;
                B[kk * DO_BSTR + j] = f2tf32(w2[(size_t)e * 16384 + (ci0 + kk) * 128 + j]);
            }
            __syncthreads();
#pragma unroll
            for (int ks = 0; ks < 4; ks++) {
                int acol = ci0 + ks * 8 + qc;
                uint32_t af[2][4];
#pragma unroll
                for (int mt = 0; mt < 2; mt++) {
                    int base = (wm * 32 + mt * 16) * DO_ASTR;
                    af[mt][0] = AU[base + qr * DO_ASTR + acol];
                    af[mt][1] = AU[base + (qr + 8) * DO_ASTR + acol];
                    af[mt][2] = AU[base + qr * DO_ASTR + acol + 4];
                    af[mt][3] = AU[base + (qr + 8) * DO_ASTR + acol + 4];
                }
                int br0 = (ks * 8 + qc) * DO_BSTR, br1 = br0 + 4 * DO_BSTR;
#pragma unroll
                for (int nt = 0; nt < 4; nt++) {
                    int j = wn * 32 + nt * 8 + qr;
                    uint32_t b0 = B[br0 + j], b1v = B[br1 + j];
                    mma_tf32(acc2[0][nt], af[0][0], af[0][1], af[0][2], af[0][3], b0, b1v);
                    mma_tf32(acc2[1][nt], af[1][0], af[1][1], af[1][2], af[1][3], b0, b1v);
                }
            }
        }
        __syncthreads();
    }
    // 7. stage acc2 -> Cst (reuses AU)
#pragma unroll
    for (int mt = 0; mt < 2; mt++)
#pragma unroll
        for (int nt = 0; nt < 4; nt++) {
            int tok0 = wm * 32 + mt * 16 + qr;
            int o0 = wn * 32 + nt * 8 + 2 * qc;
            float4 c = acc2[mt][nt];
            Cst[o0 * 130 + tok0] = c.x;
            Cst[(o0 + 1) * 130 + tok0] = c.y;
            Cst[o0 * 130 + tok0 + 8] = c.z;
            Cst[(o0 + 1) * 130 + tok0 + 8] = c.w;
        }
    __syncthreads();
    // 8. final write: out = x1 (+ drift for real) + delta, fp32 skip path
    int tl = t & 127, og = t >> 7;
    float g0 = G[tl], g1 = G[128 + tl], g2 = G[256 + tl], g3 = G[384 + tl];
    for (int j = 0; j < 32; j++) {
        int o = og * 32 + j;
        float delta = Cst[o * 130 + tl] +
                      g0 * b2[o] + g1 * b2[128 + o] + g2 * b2[256 + o] + g3 * b2[384 + o];
        float base;
        size_t gi;
        if (o < 64) {
            gi = ((size_t)(bt * 64 + o)) * 4096 + hw0 + tl;
            base = g_x1r[gi] + DRf[o * 130 + tl];
        } else {
            gi = IMOFF + ((size_t)(bt * 64 + o - 64)) * 4096 + hw0 + tl;
            base = g_x1i[gi - IMOFF];
        }
        out[gi] = base + delta;
    }
}

extern "C" void kernel_launch(void* const* d_in, const int* in_sizes, int n_in,
                              void* d_out, int out_size) {
    const float* x_real = (const float*)d_in[0];
    const float* x_imag = (const float*)d_in[1];
    const float* dt     = (const float*)d_in[2];
    const float* nz_r   = (const float*)d_in[3];
    const float* nz_i   = (const float*)d_in[4];
    const float* ln_s_w = (const float*)d_in[5];
    const float* ln_s_b = (const float*)d_in[6];
    const float* conv_w = (const float*)d_in[7];
    const float* conv_b = (const float*)d_in[8];
    const float* ln_t_w = (const float*)d_in[9];
    const float* ln_t_b = (const float*)d_in[10];
    const float* lam_re = (const float*)d_in[11];
    const float* lam_im = (const float*)d_in[12];
    const float* sb_re  = (const float*)d_in[13];
    const float* sb_im  = (const float*)d_in[14];
    const float* enc_re = (const float*)d_in[15];
    const float* enc_im = (const float*)d_in[16];
    const float* dec_re = (const float*)d_in[17];
    const float* dec_im = (const float*)d_in[18];
    const float* rw     = (const float*)d_in[19];
    const float* rb     = (const float*)d_in[20];
    const float* w1     = (const float*)d_in[21];
    const float* b1     = (const float*)d_in[22];
    const float* w2     = (const float*)d_in[23];
    const float* b2     = (const float*)d_in[24];
    float* out = (float*)d_out;

    int conv_smem = 128 * 130 * 4;                                 // 66560 B
    int enc_smem  = (128 * ENC_ASTR + 128 * ENC_BSTR + 256) * 4;   // 138240 B
    int out_smem  = (16896 * 2 + 8320 + 4352 + 512) * 4;           // 187904 B
    cudaFuncSetAttribute(k_conv, cudaFuncAttributeMaxDynamicSharedMemorySize, conv_smem);
    cudaFuncSetAttribute(k_enc, cudaFuncAttributeMaxDynamicSharedMemorySize, enc_smem);
    cudaFuncSetAttribute(k_out, cudaFuncAttributeMaxDynamicSharedMemorySize, out_smem);

    k_setup<<<8, 256>>>(dt, lam_re, lam_im);
    k_sln<<<2048, 256>>>(x_real, x_imag, ln_s_w, ln_s_b);
    k_conv<<<dim3(32, 32), 256, conv_smem>>>(conv_w, conv_b, x_real, x_imag);
    k_enc<<<1024, 512, enc_smem>>>(ln_t_w, ln_t_b, enc_re, enc_im, sb_re, sb_im, nz_r, nz_i);
    k_scan<<<2048, 256>>>();
    k_out<<<1024, 512, out_smem>>>(dec_re, dec_im, rw, rb, w1, b1, w2, b2, out);
}

// round 8
// speedup vs baseline: 1.7184x; 1.1010x over previous
#include <cuda_runtime.h>
#include <math.h>
#include <stdint.h>

#define BT 32
#define DIM 64
#define HW 4096
#define IMOFF 8388608
#define LNEPS 1e-5f

// ---------------- scratch ----------------
__device__ __align__(16) float g_xc[(size_t)BT * HW * 128];   // LN'd conv input (pixel-major, tf32-rounded)
__device__ __align__(16) float g_x1r[(size_t)BT * DIM * HW];
__device__ __align__(16) float g_x1i[(size_t)BT * DIM * HW];
__device__ float g_ar[BT * DIM], g_ai[BT * DIM], g_fr[BT * DIM], g_fi[BT * DIM], g_sq[BT];

__device__ __forceinline__ float gelu_tanh(float x) {
    float t = 0.7978845608028654f * (x + 0.044715f * x * x * x);
    return 0.5f * x * (1.0f + tanhf(t));
}
__device__ __forceinline__ uint32_t f2tf32(float f) {
    uint32_t u; asm("cvt.rna.tf32.f32 %0, %1;" : "=r"(u) : "f"(f)); return u;
}
__device__ __forceinline__ void mma_tf32(float4& c, uint32_t a0, uint32_t a1, uint32_t a2,
                                         uint32_t a3, uint32_t b0, uint32_t b1) {
    asm volatile("mma.sync.aligned.m16n8k8.row.col.f32.tf32.tf32.f32 "
                 "{%0,%1,%2,%3}, {%4,%5,%6,%7}, {%8,%9}, {%0,%1,%2,%3};"
                 : "+f"(c.x), "+f"(c.y), "+f"(c.z), "+f"(c.w)
                 : "r"(a0), "r"(a1), "r"(a2), "r"(a3), "r"(b0), "r"(b1));
}

// ---------------- K0: per-(b,t,d) decay & forcing ----------------
__global__ void k_setup(const float* __restrict__ dt, const float* __restrict__ lam_re,
                        const float* __restrict__ lam_im) {
    int i = blockIdx.x * blockDim.x + threadIdx.x;
    if (i >= BT * DIM) return;
    int bt = i >> 6, d = i & 63;
    float dtv = dt[bt];
    float x = lam_re[d];
    float sp = (x > 20.f) ? x : log1pf(expf(x));
    float lr = -sp, li = lam_im[d];
    float er = expf(lr * dtv);
    float ar = er * cosf(li * dtv), ai = er * sinf(li * dtv);
    float den = lr * lr + li * li;
    g_ar[i] = ar; g_ai[i] = ai;
    g_fr[i] = ((ar - 1.f) * lr + ai * li) / den;
    g_fi[i] = (ai * lr - (ar - 1.f) * li) / den;
    if (d == 0) g_sq[bt] = 0.01f * sqrtf(dtv);
}

// ---------------- K1: spatial complex LayerNorm -> g_xc (tf32-rounded) ----------------
__global__ void k_sln(const float* __restrict__ xr, const float* __restrict__ xi,
                      const float* __restrict__ w, const float* __restrict__ b) {
    __shared__ float sh[128][65];
    __shared__ float smu[64], srs[64];
    int t = threadIdx.x;
    int p0 = blockIdx.x * 64;
    int bt = p0 >> 12, hw0 = p0 & 4095;
    for (int r = 0; r < 32; r++) {
        int idx = t + 256 * r;
        int c = idx >> 6, p = idx & 63;
        float v = (c < 64) ? xr[((size_t)(bt * 64 + c)) * 4096 + hw0 + p]
                           : xi[((size_t)(bt * 64 + c - 64)) * 4096 + hw0 + p];
        sh[c][p] = v;
    }
    __syncthreads();
    int wid = t >> 5, lane = t & 31;
    if (wid < 8) {
        for (int pp = 0; pp < 8; pp++) {
            int p = wid * 8 + pp;
            float s = 0.f, s2 = 0.f;
            for (int cc = lane; cc < 128; cc += 32) {
                float v = sh[cc][p]; s += v; s2 += v * v;
            }
            for (int o = 16; o; o >>= 1) {
                s += __shfl_xor_sync(0xffffffffu, s, o);
                s2 += __shfl_xor_sync(0xffffffffu, s2, o);
            }
            if (lane == 0) {
                float mu = s * (1.f / 128.f);
                smu[p] = mu;
                srs[p] = rsqrtf(s2 * (1.f / 128.f) - mu * mu + LNEPS);
            }
        }
    }
    __syncthreads();
    for (int r = 0; r < 32; r++) {
        int idx = t + 256 * r;
        int p = idx >> 7, c = idx & 127;
        float v = (sh[c][p] - smu[p]) * srs[p] * w[c] + b[c];
        g_xc[((size_t)(p0 + p)) * 128 + c] = __uint_as_float(f2tf32(v));
    }
}

// ---------------- K2: 3x3 conv via tf32 mma, + bias + residual -> x1 ----------------
#define CONV_ASTR 36
#define CONV_BSTR 136
__global__ void k_conv(const float* __restrict__ cw, const float* __restrict__ cb,
                       const float* __restrict__ xr, const float* __restrict__ xi) {
    extern __shared__ uint32_t cs[];
    uint32_t* A = cs;                  // [264][36]
    uint32_t* B = cs + 264 * CONV_ASTR;// [32][136]
    float* Cst = (float*)cs;           // epilogue stage [128 co][130]
    int t = threadIdx.x;
    int h0 = blockIdx.x * 2, bt = blockIdx.y;
    int wrp = t >> 5, lane = t & 31;
    int wm = wrp & 3, wn = wrp >> 2;
    int qr = lane >> 2, qc = lane & 3;
    float4 acc[2][8];
#pragma unroll
    for (int i = 0; i < 2; i++)
#pragma unroll
        for (int j = 0; j < 8; j++) acc[i][j] = make_float4(0, 0, 0, 0);

    for (int kc = 0; kc < 4; kc++) {
        int ci0 = kc * 32;
        __syncthreads();
        for (int r = 0; r < 4; r++) {
            int gh = h0 + r - 1;
            for (int idx = t; idx < 2112; idx += 256) {
                int xx = idx >> 5, c = idx & 31;
                int gw = xx - 1;
                float v = 0.f;
                if ((unsigned)gh < 64u && (unsigned)gw < 64u)
                    v = g_xc[((size_t)(bt * 4096 + gh * 64 + gw)) * 128 + ci0 + c];
                A[(r * 66 + xx) * CONV_ASTR + c] = __float_as_uint(v);
            }
        }
        for (int tap = 0; tap < 9; tap++) {
            int dy = tap / 3 - 1, dx = tap % 3 - 1;
            __syncthreads();
            for (int idx = t; idx < 4096; idx += 256) {
                int kk = idx >> 7, co = idx & 127;
                B[kk * CONV_BSTR + co] = f2tf32(cw[((size_t)(tap * 128 + ci0 + kk)) * 128 + co]);
            }
            __syncthreads();
            int prs[4];
#pragma unroll
            for (int i = 0; i < 4; i++) {
                int m = wm * 32 + i * 8 + qr;
                int y = m >> 6, x = m & 63;
                prs[i] = (y + dy + 1) * 66 + (x + dx + 1);
            }
#pragma unroll
            for (int ks = 0; ks < 4; ks++) {
                int acol = ks * 8 + qc;
                uint32_t af[4][2];
#pragma unroll
                for (int i = 0; i < 4; i++) {
                    af[i][0] = A[prs[i] * CONV_ASTR + acol];
                    af[i][1] = A[prs[i] * CONV_ASTR + acol + 4];
                }
                int brow0 = (ks * 8 + qc) * CONV_BSTR;
                int brow1 = brow0 + 4 * CONV_BSTR;
#pragma unroll
                for (int nt = 0; nt < 8; nt++) {
                    int co = wn * 64 + nt * 8 + qr;
                    uint32_t b0 = B[brow0 + co], b1 = B[brow1 + co];
                    mma_tf32(acc[0][nt], af[0][0], af[1][0], af[0][1], af[1][1], b0, b1);
                    mma_tf32(acc[1][nt], af[2][0], af[3][0], af[2][1], af[3][1], b0, b1);
                }
            }
        }
    }
    __syncthreads();
#pragma unroll
    for (int mt = 0; mt < 2; mt++)
#pragma unroll
        for (int nt = 0; nt < 8; nt++) {
            int m0 = wm * 32 + mt * 16 + qr;
            int n0 = wn * 64 + nt * 8 + 2 * qc;
            float4 c = acc[mt][nt];
            Cst[n0 * 130 + m0] = c.x;
            Cst[(n0 + 1) * 130 + m0] = c.y;
            Cst[n0 * 130 + m0 + 8] = c.z;
            Cst[(n0 + 1) * 130 + m0 + 8] = c.w;
        }
    __syncthreads();
    int p = t & 127, og = t >> 7;
    size_t pb = (size_t)h0 * 64 + p;
    for (int j = 0; j < 64; j++) {
        int co = og * 64 + j;
        float v = Cst[co * 130 + p] + cb[co];
        if (co < 64) {
            size_t gi = ((size_t)(bt * 64 + co)) * 4096 + pb;
            g_x1r[gi] = v + xr[gi];
        } else {
            size_t gi = ((size_t)(bt * 64 + co - 64)) * 4096 + pb;
            g_x1i[gi] = v + xi[gi];
        }
    }
}

// ---------------- K3: temporal mega-kernel ----------------
// block = (b, 8 hw-positions) x all 16 timesteps = 128 tokens (tok = tt*8 + hwi).
// LN -> encode mma -> forcing+noise -> in-smem scan -> decode mma -> residual
// -> gates -> MoE (HS halved) -> single out write. No global intermediates.
#define MT_ASTR 132
__global__ __launch_bounds__(512, 1) void k_temp(
        const float* __restrict__ ltw, const float* __restrict__ ltb,
        const float* __restrict__ encr, const float* __restrict__ enci,
        const float* __restrict__ sbr, const float* __restrict__ sbi,
        const float* __restrict__ nzr, const float* __restrict__ nzi,
        const float* __restrict__ decr, const float* __restrict__ deci,
        const float* __restrict__ rw, const float* __restrict__ rb,
        const float* __restrict__ w1, const float* __restrict__ b1,
        const float* __restrict__ w2, const float* __restrict__ b2,
        float* __restrict__ out) {
    extern __shared__ uint32_t ts[];
    float*    X1   = (float*)ts;            // [128 tok][132 c] fp32 base (persists)
    uint32_t* WORK = ts + 16896;            // [128][132] staged: LN->Cst->u->h->tok->Cst
    uint32_t* HSB  = ts + 2 * 16896;        // 8704 w: DR [64][130] then HS [128][68]
    uint32_t* B    = ts + 2 * 16896 + 8704; // [32][136] = 4352 w
    float*    G    = (float*)(ts + 2 * 16896 + 8704 + 4352);  // [4][128]
    float*    smu  = G + 512;
    float*    srs  = smu + 128;
    float* WORKf = (float*)WORK;
    float* DRf   = (float*)HSB;
    float* CstF  = (float*)WORK;
    int t = threadIdx.x;
    int hw0 = blockIdx.x * 8;
    int b = blockIdx.y;
    int wrp = t >> 5, lane = t & 31;
    int wm = wrp & 3, wn = wrp >> 2;
    int qr = lane >> 2, qc = lane & 3;

    // ---- 1. load x1 tile (fp32) ----
    for (int r = 0; r < 32; r++) {
        int idx = t + 512 * r;
        int hwi = idx & 7, c = (idx >> 3) & 127, tt = idx >> 10;
        int bt = b * 16 + tt;
        float v = (c < 64) ? g_x1r[((size_t)(bt * 64 + c)) * 4096 + hw0 + hwi]
                           : g_x1i[((size_t)(bt * 64 + c - 64)) * 4096 + hw0 + hwi];
        X1[(tt * 8 + hwi) * MT_ASTR + c] = v;
    }
    __syncthreads();
    // ---- 2. LN -> WORK (tf32) ----
    for (int sub = 0; sub < 8; sub++) {
        int tok = wrp * 8 + sub;
        float s = 0.f, s2 = 0.f;
        for (int k = lane; k < 128; k += 32) {
            float v = X1[tok * MT_ASTR + k]; s += v; s2 += v * v;
        }
        for (int o = 16; o; o >>= 1) {
            s += __shfl_xor_sync(0xffffffffu, s, o);
            s2 += __shfl_xor_sync(0xffffffffu, s2, o);
        }
        if (lane == 0) {
            float mu = s * (1.f / 128.f);
            smu[tok] = mu;
            srs[tok] = rsqrtf(s2 * (1.f / 128.f) - mu * mu + LNEPS);
        }
    }
    __syncthreads();
    for (int r = 0; r < 32; r++) {
        int idx = t + 512 * r;
        int tok = idx >> 7, k = idx & 127;
        float v = (X1[tok * MT_ASTR + k] - smu[tok]) * srs[tok] * ltw[k] + ltb[k];
        WORK[tok * MT_ASTR + k] = f2tf32(v);
    }
    // ---- 3. encode mma (128x128x128, 4 k-chunks) ----
    {
        float4 acc[2][4];
#pragma unroll
        for (int i = 0; i < 2; i++)
#pragma unroll
            for (int j = 0; j < 4; j++) acc[i][j] = make_float4(0, 0, 0, 0);
        for (int kc = 0; kc < 4; kc++) {
            __syncthreads();
            for (int r = 0; r < 8; r++) {
                int idx = t + 512 * r;
                int kk = idx >> 7, j = idx & 127;
                int k = kc * 32 + kk;
                float v;
                if (k < 64) v = (j < 64) ? encr[k * 64 + j] : enci[k * 64 + (j - 64)];
                else { int k2 = k - 64;
                       v = (j < 64) ? -enci[k2 * 64 + j] : encr[k2 * 64 + (j - 64)]; }
                B[kk * 136 + j] = f2tf32(v);
            }
            __syncthreads();
#pragma unroll
            for (int ks = 0; ks < 4; ks++) {
                int acol = kc * 32 + ks * 8 + qc;
                uint32_t af[2][4];
#pragma unroll
                for (int mt = 0; mt < 2; mt++) {
                    int base = (wm * 32 + mt * 16) * MT_ASTR;
                    af[mt][0] = WORK[base + qr * MT_ASTR + acol];
                    af[mt][1] = WORK[base + (qr + 8) * MT_ASTR + acol];
                    af[mt][2] = WORK[base + qr * MT_ASTR + acol + 4];
                    af[mt][3] = WORK[base + (qr + 8) * MT_ASTR + acol + 4];
                }
                int br0 = (ks * 8 + qc) * 136, br1 = br0 + 4 * 136;
#pragma unroll
                for (int nt = 0; nt < 4; nt++) {
                    int j = wn * 32 + nt * 8 + qr;
                    uint32_t b0 = B[br0 + j], b1v = B[br1 + j];
                    mma_tf32(acc[0][nt], af[0][0], af[0][1], af[0][2], af[0][3], b0, b1v);
                    mma_tf32(acc[1][nt], af[1][0], af[1][1], af[1][2], af[1][3], b0, b1v);
                }
            }
        }
        __syncthreads();  // all mma reads of WORK done
#pragma unroll
        for (int mt = 0; mt < 2; mt++)
#pragma unroll
            for (int nt = 0; nt < 4; nt++) {
                int tok0 = wm * 32 + mt * 16 + qr;
                int j0 = wn * 32 + nt * 8 + 2 * qc;
                float4 c = acc[mt][nt];
                CstF[j0 * 130 + tok0] = c.x;
                CstF[(j0 + 1) * 130 + tok0] = c.y;
                CstF[j0 * 130 + tok0 + 8] = c.z;
                CstF[(j0 + 1) * 130 + tok0 + 8] = c.w;
            }
    }
    __syncthreads();
    // ---- 4. forcing + noise -> u (regs), then write into WORK[tok][128] ----
    {
        float ureg[32];
        for (int r = 0; r < 16; r++) {
            int p = t + 512 * r;
            int e = p & 63, tok = p >> 6;
            int tt = tok >> 3, hwi = tok & 7;
            int bt = b * 16 + tt;
            int ai_ = bt * 64 + e;
            float ur = CstF[e * 130 + tok] + sbr[e];
            float ui = CstF[(e + 64) * 130 + tok] + sbi[e];
            float fr = g_fr[ai_], fi_ = g_fi[ai_], sq = g_sq[bt];
            size_t nb = ((size_t)(b * 4096 + hw0 + hwi) * 16 + tt) * 64 + e;
            ureg[2 * r]     = ur * fr - ui * fi_ + sq * nzr[nb];
            ureg[2 * r + 1] = ur * fi_ + ui * fr + sq * nzi[nb];
        }
        __syncthreads();
        for (int r = 0; r < 16; r++) {
            int p = t + 512 * r;
            int e = p & 63, tok = p >> 6;
            WORK[tok * MT_ASTR + e]      = __float_as_uint(ureg[2 * r]);
            WORK[tok * MT_ASTR + 64 + e] = __float_as_uint(ureg[2 * r + 1]);
        }
    }
    __syncthreads();
    // ---- 5. scan over tt (in smem), write h as tf32 ----
    {
        int e = t & 63, hwi = t >> 6;
        float hr = 0.f, hi = 0.f;
        for (int tt = 0; tt < 16; tt++) {
            int tok = tt * 8 + hwi;
            float ur = WORKf[tok * MT_ASTR + e];
            float ui = WORKf[tok * MT_ASTR + 64 + e];
            int ai_ = (b * 16 + tt) * 64 + e;
            float ar = g_ar[ai_], aiv = g_ai[ai_];
            float nhr = ar * hr - aiv * hi + ur;
            float nhi = ar * hi + aiv * hr + ui;
            hr = nhr; hi = nhi;
            WORK[tok * MT_ASTR + e]      = f2tf32(hr);
            WORK[tok * MT_ASTR + 64 + e] = f2tf32(hi);
        }
    }
    __syncthreads();
    // ---- 6. decode mma (128x64x128) -> DR ----
    {
        float4 dacc[2][2];
#pragma unroll
        for (int i = 0; i < 2; i++)
#pragma unroll
            for (int j = 0; j < 2; j++) dacc[i][j] = make_float4(0, 0, 0, 0);
        for (int kc = 0; kc < 4; kc++) {
            __syncthreads();
            for (int r = 0; r < 4; r++) {
                int idx = t + 512 * r;
                int kk = idx >> 6, d = idx & 63;
                int k = kc * 32 + kk;
                float v = (k < 64) ? decr[k * 64 + d] : -deci[(k - 64) * 64 + d];
                B[kk * 72 + d] = f2tf32(v);
            }
            __syncthreads();
#pragma unroll
            for (int ks = 0; ks < 4; ks++) {
                int acol = kc * 32 + ks * 8 + qc;
                uint32_t af[2][4];
#pragma unroll
                for (int mt = 0; mt < 2; mt++) {
                    int base = (wm * 32 + mt * 16) * MT_ASTR;
                    af[mt][0] = WORK[base + qr * MT_ASTR + acol];
                    af[mt][1] = WORK[base + (qr + 8) * MT_ASTR + acol];
                    af[mt][2] = WORK[base + qr * MT_ASTR + acol + 4];
                    af[mt][3] = WORK[base + (qr + 8) * MT_ASTR + acol + 4];
                }
                int br0 = (ks * 8 + qc) * 72, br1 = br0 + 4 * 72;
#pragma unroll
                for (int nt = 0; nt < 2; nt++) {
                    int j = wn * 16 + nt * 8 + qr;
                    uint32_t b0 = B[br0 + j], b1v = B[br1 + j];
                    mma_tf32(dacc[0][nt], af[0][0], af[0][1], af[0][2], af[0][3], b0, b1v);
                    mma_tf32(dacc[1][nt], af[1][0], af[1][1], af[1][2], af[1][3], b0, b1v);
                }
            }
        }
        __syncthreads();
#pragma unroll
        for (int mt = 0; mt < 2; mt++)
#pragma unroll
            for (int nt = 0; nt < 2; nt++) {
                int tok0 = wm * 32 + mt * 16 + qr;
                int d0 = wn * 16 + nt * 8 + 2 * qc;
                float4 c = dacc[mt][nt];
                DRf[d0 * 130 + tok0] = c.x;
                DRf[(d0 + 1) * 130 + tok0] = c.y;
                DRf[d0 * 130 + tok0 + 8] = c.z;
                DRf[(d0 + 1) * 130 + tok0 + 8] = c.w;
            }
    }
    __syncthreads();
    // ---- 7. base = x1 + drift (fp32, in X1); tokens (tf32) -> WORK ----
    for (int r = 0; r < 32; r++) {
        int idx = t + 512 * r;
        int tok = idx >> 7, c = idx & 127;
        float v = X1[tok * MT_ASTR + c];
        if (c < 64) v += DRf[c * 130 + tok];
        X1[tok * MT_ASTR + c] = v;
        WORK[tok * MT_ASTR + c] = f2tf32(v);
    }
    __syncthreads();
    // ---- 8. gates ----
    {
        int tok = t & 127, e = t >> 7;
        float l = rb[e];
        for (int c = 0; c < 128; c++)
            l = fmaf(WORKf[tok * MT_ASTR + c], rw[c * 4 + e], l);
        G[e * 128 + tok] = l;
    }
    __syncthreads();
    if (t < 128) {
        float l0 = G[t], l1 = G[128 + t], l2 = G[256 + t], l3 = G[384 + t];
        float m = fmaxf(fmaxf(l0, l1), fmaxf(l2, l3));
        float e0 = expf(l0 - m), e1 = expf(l1 - m), e2 = expf(l2 - m), e3 = expf(l3 - m);
        float inv = 1.f / (e0 + e1 + e2 + e3);
        G[t] = e0 * inv; G[128 + t] = e1 * inv;
        G[256 + t] = e2 * inv; G[384 + t] = e3 * inv;
    }
    // ---- 9. MoE: 4 experts x 2 HS-halves ----
    float4 acc2[2][4];
#pragma unroll
    for (int i = 0; i < 2; i++)
#pragma unroll
        for (int j = 0; j < 4; j++) acc2[i][j] = make_float4(0, 0, 0, 0);

    for (int e = 0; e < 4; e++) {
        for (int half = 0; half < 2; half++) {
            float4 acc1[2][2];
#pragma unroll
            for (int i = 0; i < 2; i++)
#pragma unroll
                for (int j = 0; j < 2; j++) acc1[i][j] = make_float4(0, 0, 0, 0);
            // GEMM1: TOK(WORK) @ w1[e][:, half*64 .. half*64+63]
            for (int kc = 0; kc < 4; kc++) {
                __syncthreads();
                for (int r = 0; r < 4; r++) {
                    int idx = t + 512 * r;
                    int kk = idx >> 6, j = idx & 63;
                    B[kk * 72 + j] = f2tf32(
                        w1[(size_t)e * 16384 + (kc * 32 + kk) * 128 + half * 64 + j]);
                }
                __syncthreads();
#pragma unroll
                for (int ks = 0; ks < 4; ks++) {
                    int acol = kc * 32 + ks * 8 + qc;
                    uint32_t af[2][4];
#pragma unroll
                    for (int mt = 0; mt < 2; mt++) {
                        int base = (wm * 32 + mt * 16) * MT_ASTR;
                        af[mt][0] = WORK[base + qr * MT_ASTR + acol];
                        af[mt][1] = WORK[base + (qr + 8) * MT_ASTR + acol];
                        af[mt][2] = WORK[base + qr * MT_ASTR + acol + 4];
                        af[mt][3] = WORK[base + (qr + 8) * MT_ASTR + acol + 4];
                    }
                    int br0 = (ks * 8 + qc) * 72, br1 = br0 + 4 * 72;
#pragma unroll
                    for (int nt = 0; nt < 2; nt++) {
                        int j = wn * 16 + nt * 8 + qr;
                        uint32_t b0 = B[br0 + j], b1v = B[br1 + j];
                        mma_tf32(acc1[0][nt], af[0][0], af[0][1], af[0][2], af[0][3], b0, b1v);
                        mma_tf32(acc1[1][nt], af[1][0], af[1][1], af[1][2], af[1][3], b0, b1v);
                    }
                }
            }
            __syncthreads();
            // epilogue: bias + gelu * gate -> HS [128][68]
#pragma unroll
            for (int mt = 0; mt < 2; mt++)
#pragma unroll
                for (int nt = 0; nt < 2; nt++) {
                    int tok0 = wm * 32 + mt * 16 + qr;
                    int jj0 = wn * 16 + nt * 8 + 2 * qc;
                    int jg = half * 64 + jj0;
                    float4 c = acc1[mt][nt];
                    float b1v0 = b1[e * 128 + jg], b1v1 = b1[e * 128 + jg + 1];
                    float g0 = G[e * 128 + tok0], g8 = G[e * 128 + tok0 + 8];
                    HSB[tok0 * 68 + jj0]           = f2tf32(gelu_tanh(c.x + b1v0) * g0);
                    HSB[tok0 * 68 + jj0 + 1]       = f2tf32(gelu_tanh(c.y + b1v1) * g0);
                    HSB[(tok0 + 8) * 68 + jj0]     = f2tf32(gelu_tanh(c.z + b1v0) * g8);
                    HSB[(tok0 + 8) * 68 + jj0 + 1] = f2tf32(gelu_tanh(c.w + b1v1) * g8);
                }
            // GEMM2: HS(half) @ w2[e][half*64 .. , :] -> acc2
            for (int kc2 = 0; kc2 < 2; kc2++) {
                __syncthreads();
                for (int r = 0; r < 8; r++) {
                    int idx = t + 512 * r;
                    int kk = idx >> 7, jo = idx & 127;
                    int khid = half * 64 + kc2 * 32 + kk;
                    B[kk * 136 + jo] = f2tf32(w2[(size_t)e * 16384 + khid * 128 + jo]);
                }
                __syncthreads();
#pragma unroll
                for (int ks = 0; ks < 4; ks++) {
                    int acol = kc2 * 32 + ks * 8 + qc;
                    uint32_t af[2][4];
#pragma unroll
                    for (int mt = 0; mt < 2; mt++) {
                        int base = (wm * 32 + mt * 16) * 68;
                        af[mt][0] = HSB[base + qr * 68 + acol];
                        af[mt][1] = HSB[base + (qr + 8) * 68 + acol];
                        af[mt][2] = HSB[base + qr * 68 + acol + 4];
                        af[mt][3] = HSB[base + (qr + 8) * 68 + acol + 4];
                    }
                    int br0 = (ks * 8 + qc) * 136, br1 = br0 + 4 * 136;
#pragma unroll
                    for (int nt = 0; nt < 4; nt++) {
                        int j = wn * 32 + nt * 8 + qr;
                        uint32_t b0 = B[br0 + j], b1v = B[br1 + j];
                        mma_tf32(acc2[0][nt], af[0][0], af[0][1], af[0][2], af[0][3], b0, b1v);
                        mma_tf32(acc2[1][nt], af[1][0], af[1][1], af[1][2], af[1][3], b0, b1v);
                    }
                }
            }
        }
    }
    __syncthreads();
    // ---- 10. stage acc2 -> Cst (WORK free) ----
#pragma unroll
    for (int mt = 0; mt < 2; mt++)
#pragma unroll
        for (int nt = 0; nt < 4; nt++) {
            int tok0 = wm * 32 + mt * 16 + qr;
            int o0 = wn * 32 + nt * 8 + 2 * qc;
            float4 c = acc2[mt][nt];
            CstF[o0 * 130 + tok0] = c.x;
            CstF[(o0 + 1) * 130 + tok0] = c.y;
            CstF[o0 * 130 + tok0 + 8] = c.z;
            CstF[(o0 + 1) * 130 + tok0 + 8] = c.w;
        }
    __syncthreads();
    // ---- 11. final write: out = base + delta ----
    {
        int tl = t & 127, og = t >> 7;
        float g0 = G[tl], g1 = G[128 + tl], g2 = G[256 + tl], g3 = G[384 + tl];
        int tt = tl >> 3, hwi = tl & 7;
        int bt = b * 16 + tt;
        for (int j = 0; j < 32; j++) {
            int o = og * 32 + j;
            float delta = CstF[o * 130 + tl] +
                          g0 * b2[o] + g1 * b2[128 + o] + g2 * b2[256 + o] + g3 * b2[384 + o];
            float base = X1[tl * MT_ASTR + o];
            size_t gi = (o < 64)
                ? ((size_t)(bt * 64 + o)) * 4096 + hw0 + hwi
                : IMOFF + ((size_t)(bt * 64 + o - 64)) * 4096 + hw0 + hwi;
            out[gi] = base + delta;
        }
    }
}

extern "C" void kernel_launch(void* const* d_in, const int* in_sizes, int n_in,
                              void* d_out, int out_size) {
    const float* x_real = (const float*)d_in[0];
    const float* x_imag = (const float*)d_in[1];
    const float* dt     = (const float*)d_in[2];
    const float* nz_r   = (const float*)d_in[3];
    const float* nz_i   = (const float*)d_in[4];
    const float* ln_s_w = (const float*)d_in[5];
    const float* ln_s_b = (const float*)d_in[6];
    const float* conv_w = (const float*)d_in[7];
    const float* conv_b = (const float*)d_in[8];
    const float* ln_t_w = (const float*)d_in[9];
    const float* ln_t_b = (const float*)d_in[10];
    const float* lam_re = (const float*)d_in[11];
    const float* lam_im = (const float*)d_in[12];
    const float* sb_re  = (const float*)d_in[13];
    const float* sb_im  = (const float*)d_in[14];
    const float* enc_re = (const float*)d_in[15];
    const float* enc_im = (const float*)d_in[16];
    const float* dec_re = (const float*)d_in[17];
    const float* dec_im = (const float*)d_in[18];
    const float* rw     = (const float*)d_in[19];
    const float* rb     = (const float*)d_in[20];
    const float* w1     = (const float*)d_in[21];
    const float* b1     = (const float*)d_in[22];
    const float* w2     = (const float*)d_in[23];
    const float* b2     = (const float*)d_in[24];
    float* out = (float*)d_out;

    int conv_smem = 128 * 130 * 4;                                      // 66560 B
    int temp_smem = (2 * 16896 + 8704 + 4352 + 512 + 256) * 4;          // 190464 B
    cudaFuncSetAttribute(k_conv, cudaFuncAttributeMaxDynamicSharedMemorySize, conv_smem);
    cudaFuncSetAttribute(k_temp, cudaFuncAttributeMaxDynamicSharedMemorySize, temp_smem);

    k_setup<<<8, 256>>>(dt, lam_re, lam_im);
    k_sln<<<2048, 256>>>(x_real, x_imag, ln_s_w, ln_s_b);
    k_conv<<<dim3(32, 32), 256, conv_smem>>>(conv_w, conv_b, x_real, x_imag);
    k_temp<<<dim3(512, 2), 512, temp_smem>>>(ln_t_w, ln_t_b, enc_re, enc_im,
                                             sb_re, sb_im, nz_r, nz_i,
                                             dec_re, dec_im, rw, rb,
                                             w1, b1, w2, b2, out);
}

// round 11
// speedup vs baseline: 2.1258x; 1.2371x over previous
#include <cuda_runtime.h>
#include <math.h>
#include <stdint.h>

#define BT 32
#define DIM 64
#define HW 4096
#define IMOFF 8388608
#define LNEPS 1e-5f

// ---------------- scratch ----------------
__device__ __align__(16) float g_xc[(size_t)BT * HW * 128];   // LN'd conv input (pixel-major, tf32-rounded)
__device__ __align__(16) float g_x1r[(size_t)BT * DIM * HW];
__device__ __align__(16) float g_x1i[(size_t)BT * DIM * HW];
__device__ float g_ar[BT * DIM], g_ai[BT * DIM], g_fr[BT * DIM], g_fi[BT * DIM], g_sq[BT];
// pre-converted tf32 weights
__device__ __align__(16) uint32_t g_encB[128 * 128];   // [k][j] packed complex encode
__device__ __align__(16) uint32_t g_decB[128 * 64];    // [k][d] packed real-part decode
__device__ __align__(16) uint32_t g_w1t[4 * 16384];
__device__ __align__(16) uint32_t g_w2t[4 * 16384];
__device__ __align__(16) uint32_t g_cwt[9 * 128 * 128];

__device__ __forceinline__ float gelu_tanh(float x) {
    float t = 0.7978845608028654f * (x + 0.044715f * x * x * x);
    return 0.5f * x * (1.0f + tanhf(t));
}
__device__ __forceinline__ uint32_t f2tf32(float f) {
    uint32_t u; asm("cvt.rna.tf32.f32 %0, %1;" : "=r"(u) : "f"(f)); return u;
}
__device__ __forceinline__ void mma_tf32(float4& c, uint32_t a0, uint32_t a1, uint32_t a2,
                                         uint32_t a3, uint32_t b0, uint32_t b1) {
    asm volatile("mma.sync.aligned.m16n8k8.row.col.f32.tf32.tf32.f32 "
                 "{%0,%1,%2,%3}, {%4,%5,%6,%7}, {%8,%9}, {%0,%1,%2,%3};"
                 : "+f"(c.x), "+f"(c.y), "+f"(c.z), "+f"(c.w)
                 : "r"(a0), "r"(a1), "r"(a2), "r"(a3), "r"(b0), "r"(b1));
}

// ---------------- K-1: weight pre-conversion (tf32, packed) ----------------
__global__ void k_wprep(const float* __restrict__ encr, const float* __restrict__ enci,
                        const float* __restrict__ decr, const float* __restrict__ deci,
                        const float* __restrict__ w1, const float* __restrict__ w2,
                        const float* __restrict__ cw) {
    int i = blockIdx.x * 256 + threadIdx.x;
    if (i < 16384) {
        int k = i >> 7, j = i & 127;
        float v;
        if (k < 64) v = (j < 64) ? encr[k * 64 + j] : enci[k * 64 + j - 64];
        else { int k2 = k - 64;
               v = (j < 64) ? -enci[k2 * 64 + j] : encr[k2 * 64 + j - 64]; }
        g_encB[i] = f2tf32(v);
    }
    if (i < 8192) {
        int k = i >> 6, d = i & 63;
        float v = (k < 64) ? decr[k * 64 + d] : -deci[(k - 64) * 64 + d];
        g_decB[i] = f2tf32(v);
    }
    if (i < 65536) {
        g_w1t[i] = f2tf32(w1[i]);
        g_w2t[i] = f2tf32(w2[i]);
    }
    if (i < 147456) g_cwt[i] = f2tf32(cw[i]);
}

// ---------------- K0: per-(b,t,d) decay & forcing ----------------
__global__ void k_setup(const float* __restrict__ dt, const float* __restrict__ lam_re,
                        const float* __restrict__ lam_im) {
    int i = blockIdx.x * blockDim.x + threadIdx.x;
    if (i >= BT * DIM) return;
    int bt = i >> 6, d = i & 63;
    float dtv = dt[bt];
    float x = lam_re[d];
    float sp = (x > 20.f) ? x : log1pf(expf(x));
    float lr = -sp, li = lam_im[d];
    float er = expf(lr * dtv);
    float ar = er * cosf(li * dtv), ai = er * sinf(li * dtv);
    float den = lr * lr + li * li;
    g_ar[i] = ar; g_ai[i] = ai;
    g_fr[i] = ((ar - 1.f) * lr + ai * li) / den;
    g_fi[i] = (ai * lr - (ar - 1.f) * li) / den;
    if (d == 0) g_sq[bt] = 0.01f * sqrtf(dtv);
}

// ---------------- K1: spatial complex LayerNorm -> g_xc (tf32-rounded) ----------------
__global__ void k_sln(const float* __restrict__ xr, const float* __restrict__ xi,
                      const float* __restrict__ w, const float* __restrict__ b) {
    __shared__ float sh[128][65];
    __shared__ float smu[64], srs[64];
    int t = threadIdx.x;
    int p0 = blockIdx.x * 64;
    int bt = p0 >> 12, hw0 = p0 & 4095;
    for (int r = 0; r < 32; r++) {
        int idx = t + 256 * r;
        int c = idx >> 6, p = idx & 63;
        float v = (c < 64) ? xr[((size_t)(bt * 64 + c)) * 4096 + hw0 + p]
                           : xi[((size_t)(bt * 64 + c - 64)) * 4096 + hw0 + p];
        sh[c][p] = v;
    }
    __syncthreads();
    int wid = t >> 5, lane = t & 31;
    if (wid < 8) {
        for (int pp = 0; pp < 8; pp++) {
            int p = wid * 8 + pp;
            float s = 0.f, s2 = 0.f;
            for (int cc = lane; cc < 128; cc += 32) {
                float v = sh[cc][p]; s += v; s2 += v * v;
            }
            for (int o = 16; o; o >>= 1) {
                s += __shfl_xor_sync(0xffffffffu, s, o);
                s2 += __shfl_xor_sync(0xffffffffu, s2, o);
            }
            if (lane == 0) {
                float mu = s * (1.f / 128.f);
                smu[p] = mu;
                srs[p] = rsqrtf(s2 * (1.f / 128.f) - mu * mu + LNEPS);
            }
        }
    }
    __syncthreads();
    for (int r = 0; r < 32; r++) {
        int idx = t + 256 * r;
        int p = idx >> 7, c = idx & 127;
        float v = (sh[c][p] - smu[p]) * srs[p] * w[c] + b[c];
        g_xc[((size_t)(p0 + p)) * 128 + c] = __uint_as_float(f2tf32(v));
    }
}

// ---------------- K2: 3x3 conv via tf32 mma, + bias + residual -> x1 ----------------
#define CONV_ASTR 36
#define CONV_BSTR 136
__global__ void k_conv(const float* __restrict__ cb,
                       const float* __restrict__ xr, const float* __restrict__ xi) {
    extern __shared__ uint32_t cs[];
    uint32_t* A = cs;                  // [264][36]
    uint32_t* B = cs + 264 * CONV_ASTR;// [32][136]
    float* Cst = (float*)cs;           // epilogue stage [128 co][130]
    int t = threadIdx.x;
    int h0 = blockIdx.x * 2, bt = blockIdx.y;
    int wrp = t >> 5, lane = t & 31;
    int wm = wrp & 3, wn = wrp >> 2;
    int qr = lane >> 2, qc = lane & 3;
    float4 acc[2][8];
#pragma unroll
    for (int i = 0; i < 2; i++)
#pragma unroll
        for (int j = 0; j < 8; j++) acc[i][j] = make_float4(0, 0, 0, 0);

    for (int kc = 0; kc < 4; kc++) {
        int ci0 = kc * 32;
        __syncthreads();
        for (int r = 0; r < 4; r++) {
            int gh = h0 + r - 1;
            for (int idx = t; idx < 2112; idx += 256) {
                int xx = idx >> 5, c = idx & 31;
                int gw = xx - 1;
                float v = 0.f;
                if ((unsigned)gh < 64u && (unsigned)gw < 64u)
                    v = g_xc[((size_t)(bt * 4096 + gh * 64 + gw)) * 128 + ci0 + c];
                A[(r * 66 + xx) * CONV_ASTR + c] = __float_as_uint(v);
            }
        }
        for (int tap = 0; tap < 9; tap++) {
            int dy = tap / 3 - 1, dx = tap % 3 - 1;
            __syncthreads();
            for (int r = 0; r < 4; r++) {
                int idx = t + 256 * r;
                int kk = idx >> 5, j4 = idx & 31;
                *(uint4*)&B[kk * CONV_BSTR + j4 * 4] =
                    *(const uint4*)&g_cwt[(size_t)tap * 16384 + (ci0 + kk) * 128 + j4 * 4];
            }
            __syncthreads();
            int prs[4];
#pragma unroll
            for (int i = 0; i < 4; i++) {
                int m = wm * 32 + i * 8 + qr;
                int y = m >> 6, x = m & 63;
                prs[i] = (y + dy + 1) * 66 + (x + dx + 1);
            }
#pragma unroll
            for (int ks = 0; ks < 4; ks++) {
                int acol = ks * 8 + qc;
                uint32_t af[4][2];
#pragma unroll
                for (int i = 0; i < 4; i++) {
                    af[i][0] = A[prs[i] * CONV_ASTR + acol];
                    af[i][1] = A[prs[i] * CONV_ASTR + acol + 4];
                }
                int brow0 = (ks * 8 + qc) * CONV_BSTR;
                int brow1 = brow0 + 4 * CONV_BSTR;
#pragma unroll
                for (int nt = 0; nt < 8; nt++) {
                    int co = wn * 64 + nt * 8 + qr;
                    uint32_t b0 = B[brow0 + co], b1 = B[brow1 + co];
                    mma_tf32(acc[0][nt], af[0][0], af[1][0], af[0][1], af[1][1], b0, b1);
                    mma_tf32(acc[1][nt], af[2][0], af[3][0], af[2][1], af[3][1], b0, b1);
                }
            }
        }
    }
    __syncthreads();
#pragma unroll
    for (int mt = 0; mt < 2; mt++)
#pragma unroll
        for (int nt = 0; nt < 8; nt++) {
            int m0 = wm * 32 + mt * 16 + qr;
            int n0 = wn * 64 + nt * 8 + 2 * qc;
            float4 c = acc[mt][nt];
            Cst[n0 * 130 + m0] = c.x;
            Cst[(n0 + 1) * 130 + m0] = c.y;
            Cst[n0 * 130 + m0 + 8] = c.z;
            Cst[(n0 + 1) * 130 + m0 + 8] = c.w;
        }
    __syncthreads();
    int p = t & 127, og = t >> 7;
    size_t pb = (size_t)h0 * 64 + p;
    for (int j = 0; j < 64; j++) {
        int co = og * 64 + j;
        float v = Cst[co * 130 + p] + cb[co];
        if (co < 64) {
            size_t gi = ((size_t)(bt * 64 + co)) * 4096 + pb;
            g_x1r[gi] = v + xr[gi];
        } else {
            size_t gi = ((size_t)(bt * 64 + co - 64)) * 4096 + pb;
            g_x1i[gi] = v + xi[gi];
        }
    }
}

// ---------------- K3: temporal mega-kernel ----------------
// block = (b, 8 hw) x 16 tt = 128 tokens. LN -> enc mma -> forcing+noise -> scan
// -> dec mma -> residual -> gates -> MoE full-width -> single out write.
#define MT_ASTR 132
__global__ __launch_bounds__(512, 1) void k_temp(
        const float* __restrict__ ltw, const float* __restrict__ ltb,
        const float* __restrict__ sbr, const float* __restrict__ sbi,
        const float* __restrict__ nzr, const float* __restrict__ nzi,
        const float* __restrict__ rw, const float* __restrict__ rb,
        const float* __restrict__ b1, const float* __restrict__ b2,
        float* __restrict__ out) {
    extern __shared__ uint32_t ts[];
    float*    X1   = (float*)ts;            // [128 tok][132 c] fp32 base (persists)
    uint32_t* WORK = ts + 16896;            // [128][132]: LN -> Cst -> u -> h -> tok -> Cst
    uint32_t* HS   = ts + 2 * 16896;        // [128][132]: DR alias, then hidden
    uint32_t* B    = ts + 3 * 16896;        // [32][136] = 4352 w
    float*    G    = (float*)(ts + 3 * 16896 + 4352);  // [4][128]
    float*    smu  = G + 512;
    float*    srs  = smu + 128;
    float* WORKf = (float*)WORK;
    float* DRf   = (float*)HS;
    float* CstF  = (float*)WORK;
    int t = threadIdx.x;
    int hw0 = blockIdx.x * 8;
    int b = blockIdx.y;
    int wrp = t >> 5, lane = t & 31;
    int wm = wrp & 3, wn = wrp >> 2;
    int qr = lane >> 2, qc = lane & 3;

    // ---- 1. load x1 tile (fp32) ----
    for (int r = 0; r < 32; r++) {
        int idx = t + 512 * r;
        int hwi = idx & 7, c = (idx >> 3) & 127, tt = idx >> 10;
        int bt = b * 16 + tt;
        float v = (c < 64) ? g_x1r[((size_t)(bt * 64 + c)) * 4096 + hw0 + hwi]
                           : g_x1i[((size_t)(bt * 64 + c - 64)) * 4096 + hw0 + hwi];
        X1[(tt * 8 + hwi) * MT_ASTR + c] = v;
    }
    __syncthreads();
    // ---- 2. LN -> WORK (tf32) ----
    for (int sub = 0; sub < 8; sub++) {
        int tok = wrp * 8 + sub;
        float s = 0.f, s2 = 0.f;
        for (int k = lane; k < 128; k += 32) {
            float v = X1[tok * MT_ASTR + k]; s += v; s2 += v * v;
        }
        for (int o = 16; o; o >>= 1) {
            s += __shfl_xor_sync(0xffffffffu, s, o);
            s2 += __shfl_xor_sync(0xffffffffu, s2, o);
        }
        if (lane == 0) {
            float mu = s * (1.f / 128.f);
            smu[tok] = mu;
            srs[tok] = rsqrtf(s2 * (1.f / 128.f) - mu * mu + LNEPS);
        }
    }
    __syncthreads();
    for (int r = 0; r < 32; r++) {
        int idx = t + 512 * r;
        int tok = idx >> 7, k = idx & 127;
        float v = (X1[tok * MT_ASTR + k] - smu[tok]) * srs[tok] * ltw[k] + ltb[k];
        WORK[tok * MT_ASTR + k] = f2tf32(v);
    }
    // ---- 3. encode mma (128x128x128, 4 k-chunks) ----
    {
        float4 acc[2][4];
#pragma unroll
        for (int i = 0; i < 2; i++)
#pragma unroll
            for (int j = 0; j < 4; j++) acc[i][j] = make_float4(0, 0, 0, 0);
        for (int kc = 0; kc < 4; kc++) {
            __syncthreads();
            for (int r = 0; r < 2; r++) {
                int idx = t + 512 * r;
                int kk = idx >> 5, j4 = idx & 31;
                *(uint4*)&B[kk * 136 + j4 * 4] =
                    *(const uint4*)&g_encB[(kc * 32 + kk) * 128 + j4 * 4];
            }
            __syncthreads();
#pragma unroll
            for (int ks = 0; ks < 4; ks++) {
                int acol = kc * 32 + ks * 8 + qc;
                uint32_t af[2][4];
#pragma unroll
                for (int mt = 0; mt < 2; mt++) {
                    int base = (wm * 32 + mt * 16) * MT_ASTR;
                    af[mt][0] = WORK[base + qr * MT_ASTR + acol];
                    af[mt][1] = WORK[base + (qr + 8) * MT_ASTR + acol];
                    af[mt][2] = WORK[base + qr * MT_ASTR + acol + 4];
                    af[mt][3] = WORK[base + (qr + 8) * MT_ASTR + acol + 4];
                }
                int br0 = (ks * 8 + qc) * 136, br1 = br0 + 4 * 136;
#pragma unroll
                for (int nt = 0; nt < 4; nt++) {
                    int j = wn * 32 + nt * 8 + qr;
                    uint32_t b0 = B[br0 + j], b1v = B[br1 + j];
                    mma_tf32(acc[0][nt], af[0][0], af[0][1], af[0][2], af[0][3], b0, b1v);
                    mma_tf32(acc[1][nt], af[1][0], af[1][1], af[1][2], af[1][3], b0, b1v);
                }
            }
        }
        __syncthreads();
#pragma unroll
        for (int mt = 0; mt < 2; mt++)
#pragma unroll
            for (int nt = 0; nt < 4; nt++) {
                int tok0 = wm * 32 + mt * 16 + qr;
                int j0 = wn * 32 + nt * 8 + 2 * qc;
                float4 c = acc[mt][nt];
                CstF[j0 * 130 + tok0] = c.x;
                CstF[(j0 + 1) * 130 + tok0] = c.y;
                CstF[j0 * 130 + tok0 + 8] = c.z;
                CstF[(j0 + 1) * 130 + tok0 + 8] = c.w;
            }
    }
    __syncthreads();
    // ---- 4. forcing + noise -> u (regs) -> WORK ----
    {
        float ureg[32];
        for (int r = 0; r < 16; r++) {
            int p = t + 512 * r;
            int e = p & 63, tok = p >> 6;
            int tt = tok >> 3, hwi = tok & 7;
            int bt = b * 16 + tt;
            int ai_ = bt * 64 + e;
            float ur = CstF[e * 130 + tok] + sbr[e];
            float ui = CstF[(e + 64) * 130 + tok] + sbi[e];
            float fr = g_fr[ai_], fi_ = g_fi[ai_], sq = g_sq[bt];
            size_t nb = ((size_t)(b * 4096 + hw0 + hwi) * 16 + tt) * 64 + e;
            ureg[2 * r]     = ur * fr - ui * fi_ + sq * nzr[nb];
            ureg[2 * r + 1] = ur * fi_ + ui * fr + sq * nzi[nb];
        }
        __syncthreads();
        for (int r = 0; r < 16; r++) {
            int p = t + 512 * r;
            int e = p & 63, tok = p >> 6;
            WORK[tok * MT_ASTR + e]      = __float_as_uint(ureg[2 * r]);
            WORK[tok * MT_ASTR + 64 + e] = __float_as_uint(ureg[2 * r + 1]);
        }
    }
    __syncthreads();
    // ---- 5. scan over tt (in smem), h as tf32 ----
    {
        int e = t & 63, hwi = t >> 6;
        float hr = 0.f, hi = 0.f;
        for (int tt = 0; tt < 16; tt++) {
            int tok = tt * 8 + hwi;
            float ur = WORKf[tok * MT_ASTR + e];
            float ui = WORKf[tok * MT_ASTR + 64 + e];
            int ai_ = (b * 16 + tt) * 64 + e;
            float ar = g_ar[ai_], aiv = g_ai[ai_];
            float nhr = ar * hr - aiv * hi + ur;
            float nhi = ar * hi + aiv * hr + ui;
            hr = nhr; hi = nhi;
            WORK[tok * MT_ASTR + e]      = f2tf32(hr);
            WORK[tok * MT_ASTR + 64 + e] = f2tf32(hi);
        }
    }
    __syncthreads();
    // ---- 6. decode mma (128x64x128) -> DR (alias HS) ----
    {
        float4 dacc[2][2];
#pragma unroll
        for (int i = 0; i < 2; i++)
#pragma unroll
            for (int j = 0; j < 2; j++) dacc[i][j] = make_float4(0, 0, 0, 0);
        for (int kc = 0; kc < 4; kc++) {
            __syncthreads();
            {
                int kk = t >> 4, d4 = t & 15;
                *(uint4*)&B[kk * 72 + d4 * 4] =
                    *(const uint4*)&g_decB[(kc * 32 + kk) * 64 + d4 * 4];
            }
            __syncthreads();
#pragma unroll
            for (int ks = 0; ks < 4; ks++) {
                int acol = kc * 32 + ks * 8 + qc;
                uint32_t af[2][4];
#pragma unroll
                for (int mt = 0; mt < 2; mt++) {
                    int base = (wm * 32 + mt * 16) * MT_ASTR;
                    af[mt][0] = WORK[base + qr * MT_ASTR + acol];
                    af[mt][1] = WORK[base + (qr + 8) * MT_ASTR + acol];
                    af[mt][2] = WORK[base + qr * MT_ASTR + acol + 4];
                    af[mt][3] = WORK[base + (qr + 8) * MT_ASTR + acol + 4];
                }
                int br0 = (ks * 8 + qc) * 72, br1 = br0 + 4 * 72;
#pragma unroll
                for (int nt = 0; nt < 2; nt++) {
                    int j = wn * 16 + nt * 8 + qr;
                    uint32_t b0 = B[br0 + j], b1v = B[br1 + j];
                    mma_tf32(dacc[0][nt], af[0][0], af[0][1], af[0][2], af[0][3], b0, b1v);
                    mma_tf32(dacc[1][nt], af[1][0], af[1][1], af[1][2], af[1][3], b0, b1v);
                }
            }
        }
        __syncthreads();
#pragma unroll
        for (int mt = 0; mt < 2; mt++)
#pragma unroll
            for (int nt = 0; nt < 2; nt++) {
                int tok0 = wm * 32 + mt * 16 + qr;
                int d0 = wn * 16 + nt * 8 + 2 * qc;
                float4 c = dacc[mt][nt];
                DRf[d0 * 130 + tok0] = c.x;
                DRf[(d0 + 1) * 130 + tok0] = c.y;
                DRf[d0 * 130 + tok0 + 8] = c.z;
                DRf[(d0 + 1) * 130 + tok0 + 8] = c.w;
            }
    }
    __syncthreads();
    // ---- 7. base = x1 + drift (fp32, in X1); tokens (tf32) -> WORK ----
    for (int r = 0; r < 32; r++) {
        int idx = t + 512 * r;
        int tok = idx >> 7, c = idx & 127;
        float v = X1[tok * MT_ASTR + c];
        if (c < 64) v += DRf[c * 130 + tok];
        X1[tok * MT_ASTR + c] = v;
        WORK[tok * MT_ASTR + c] = f2tf32(v);
    }
    __syncthreads();
    // ---- 8. gates ----
    {
        int tok = t & 127, e = t >> 7;
        float l = rb[e];
        for (int c = 0; c < 128; c++)
            l = fmaf(WORKf[tok * MT_ASTR + c], rw[c * 4 + e], l);
        G[e * 128 + tok] = l;
    }
    __syncthreads();
    if (t < 128) {
        float l0 = G[t], l1 = G[128 + t], l2 = G[256 + t], l3 = G[384 + t];
        float m = fmaxf(fmaxf(l0, l1), fmaxf(l2, l3));
        float e0 = expf(l0 - m), e1 = expf(l1 - m), e2 = expf(l2 - m), e3 = expf(l3 - m);
        float inv = 1.f / (e0 + e1 + e2 + e3);
        G[t] = e0 * inv; G[128 + t] = e1 * inv;
        G[256 + t] = e2 * inv; G[384 + t] = e3 * inv;
    }
    // ---- 9. MoE: 4 experts, full-width GEMMs ----
    float4 acc2[2][4];
#pragma unroll
    for (int i = 0; i < 2; i++)
#pragma unroll
        for (int j = 0; j < 4; j++) acc2[i][j] = make_float4(0, 0, 0, 0);

    for (int e = 0; e < 4; e++) {
        float4 acc1[2][4];
#pragma unroll
        for (int i = 0; i < 2; i++)
#pragma unroll
            for (int j = 0; j < 4; j++) acc1[i][j] = make_float4(0, 0, 0, 0);
        // GEMM1: TOK(WORK) @ w1[e] (full 128-wide)
        for (int kc = 0; kc < 4; kc++) {
            __syncthreads();
            for (int r = 0; r < 2; r++) {
                int idx = t + 512 * r;
                int kk = idx >> 5, j4 = idx & 31;
                *(uint4*)&B[kk * 136 + j4 * 4] =
                    *(const uint4*)&g_w1t[(size_t)e * 16384 + (kc * 32 + kk) * 128 + j4 * 4];
            }
            __syncthreads();
#pragma unroll
            for (int ks = 0; ks < 4; ks++) {
                int acol = kc * 32 + ks * 8 + qc;
                uint32_t af[2][4];
#pragma unroll
                for (int mt = 0; mt < 2; mt++) {
                    int base = (wm * 32 + mt * 16) * MT_ASTR;
                    af[mt][0] = WORK[base + qr * MT_ASTR + acol];
                    af[mt][1] = WORK[base + (qr + 8) * MT_ASTR + acol];
                    af[mt][2] = WORK[base + qr * MT_ASTR + acol + 4];
                    af[mt][3] = WORK[base + (qr + 8) * MT_ASTR + acol + 4];
                }
                int br0 = (ks * 8 + qc) * 136, br1 = br0 + 4 * 136;
#pragma unroll
                for (int nt = 0; nt < 4; nt++) {
                    int j = wn * 32 + nt * 8 + qr;
                    uint32_t b0 = B[br0 + j], b1v = B[br1 + j];
                    mma_tf32(acc1[0][nt], af[0][0], af[0][1], af[0][2], af[0][3], b0, b1v);
                    mma_tf32(acc1[1][nt], af[1][0], af[1][1], af[1][2], af[1][3], b0, b1v);
                }
            }
        }
        // epilogue1: bias + gelu * gate -> HS (tf32)  [prior HS reads separated by kc-loop syncs]
#pragma unroll
        for (int mt = 0; mt < 2; mt++)
#pragma unroll
            for (int nt = 0; nt < 4; nt++) {
                int tok0 = wm * 32 + mt * 16 + qr;
                int j0 = wn * 32 + nt * 8 + 2 * qc;
                float4 c = acc1[mt][nt];
                float b1v0 = b1[e * 128 + j0], b1v1 = b1[e * 128 + j0 + 1];
                float g0 = G[e * 128 + tok0], g8 = G[e * 128 + tok0 + 8];
                HS[tok0 * MT_ASTR + j0]           = f2tf32(gelu_tanh(c.x + b1v0) * g0);
                HS[tok0 * MT_ASTR + j0 + 1]       = f2tf32(gelu_tanh(c.y + b1v1) * g0);
                HS[(tok0 + 8) * MT_ASTR + j0]     = f2tf32(gelu_tanh(c.z + b1v0) * g8);
                HS[(tok0 + 8) * MT_ASTR + j0 + 1] = f2tf32(gelu_tanh(c.w + b1v1) * g8);
            }
        // GEMM2: HS @ w2[e] -> acc2
        for (int kc = 0; kc < 4; kc++) {
            __syncthreads();
            for (int r = 0; r < 2; r++) {
                int idx = t + 512 * r;
                int kk = idx >> 5, j4 = idx & 31;
                *(uint4*)&B[kk * 136 + j4 * 4] =
                    *(const uint4*)&g_w2t[(size_t)e * 16384 + (kc * 32 + kk) * 128 + j4 * 4];
            }
            __syncthreads();
#pragma unroll
            for (int ks = 0; ks < 4; ks++) {
                int acol = kc * 32 + ks * 8 + qc;
                uint32_t af[2][4];
#pragma unroll
                for (int mt = 0; mt < 2; mt++) {
                    int base = (wm * 32 + mt * 16) * MT_ASTR;
                    af[mt][0] = HS[base + qr * MT_ASTR + acol];
                    af[mt][1] = HS[base + (qr + 8) * MT_ASTR + acol];
                    af[mt][2] = HS[base + qr * MT_ASTR + acol + 4];
                    af[mt][3] = HS[base + (qr + 8) * MT_ASTR + acol + 4];
                }
                int br0 = (ks * 8 + qc) * 136, br1 = br0 + 4 * 136;
#pragma unroll
                for (int nt = 0; nt < 4; nt++) {
                    int j = wn * 32 + nt * 8 + qr;
                    uint32_t b0 = B[br0 + j], b1v = B[br1 + j];
                    mma_tf32(acc2[0][nt], af[0][0], af[0][1], af[0][2], af[0][3], b0, b1v);
                    mma_tf32(acc2[1][nt], af[1][0], af[1][1], af[1][2], af[1][3], b0, b1v);
                }
            }
        }
        __syncthreads();  // HS reads done before next expert overwrites
    }
    // ---- 10. stage acc2 -> Cst (WORK free) ----
#pragma unroll
    for (int mt = 0; mt < 2; mt++)
#pragma unroll
        for (int nt = 0; nt < 4; nt++) {
            int tok0 = wm * 32 + mt * 16 + qr;
            int o0 = wn * 32 + nt * 8 + 2 * qc;
            float4 c = acc2[mt][nt];
            CstF[o0 * 130 + tok0] = c.x;
            CstF[(o0 + 1) * 130 + tok0] = c.y;
            CstF[o0 * 130 + tok0 + 8] = c.z;
            CstF[(o0 + 1) * 130 + tok0 + 8] = c.w;
        }
    __syncthreads();
    // ---- 11. final write: out = base + delta ----
    {
        int tl = t & 127, og = t >> 7;
        float g0 = G[tl], g1 = G[128 + tl], g2 = G[256 + tl], g3 = G[384 + tl];
        int tt = tl >> 3, hwi = tl & 7;
        int bt = b * 16 + tt;
        for (int j = 0; j < 32; j++) {
            int o = og * 32 + j;
            float delta = CstF[o * 130 + tl] +
                          g0 * b2[o] + g1 * b2[128 + o] + g2 * b2[256 + o] + g3 * b2[384 + o];
            float base = X1[tl * MT_ASTR + o];
            size_t gi = (o < 64)
                ? ((size_t)(bt * 64 + o)) * 4096 + hw0 + hwi
                : IMOFF + ((size_t)(bt * 64 + o - 64)) * 4096 + hw0 + hwi;
            out[gi] = base + delta;
        }
    }
}

extern "C" void kernel_launch(void* const* d_in, const int* in_sizes, int n_in,
                              void* d_out, int out_size) {
    const float* x_real = (const float*)d_in[0];
    const float* x_imag = (const float*)d_in[1];
    const float* dt     = (const float*)d_in[2];
    const float* nz_r   = (const float*)d_in[3];
    const float* nz_i   = (const float*)d_in[4];
    const float* ln_s_w = (const float*)d_in[5];
    const float* ln_s_b = (const float*)d_in[6];
    const float* conv_w = (const float*)d_in[7];
    const float* conv_b = (const float*)d_in[8];
    const float* ln_t_w = (const float*)d_in[9];
    const float* ln_t_b = (const float*)d_in[10];
    const float* lam_re = (const float*)d_in[11];
    const float* lam_im = (const float*)d_in[12];
    const float* sb_re  = (const float*)d_in[13];
    const float* sb_im  = (const float*)d_in[14];
    const float* enc_re = (const float*)d_in[15];
    const float* enc_im = (const float*)d_in[16];
    const float* dec_re = (const float*)d_in[17];
    const float* dec_im = (const float*)d_in[18];
    const float* rw     = (const float*)d_in[19];
    const float* rb     = (const float*)d_in[20];
    const float* w1     = (const float*)d_in[21];
    const float* b1     = (const float*)d_in[22];
    const float* w2     = (const float*)d_in[23];
    const float* b2     = (const float*)d_in[24];
    float* out = (float*)d_out;

    int conv_smem = 128 * 130 * 4;                              // 66560 B
    int temp_smem = (3 * 16896 + 4352 + 512 + 256) * 4;         // 223232 B
    cudaFuncSetAttribute(k_conv, cudaFuncAttributeMaxDynamicSharedMemorySize, conv_smem);
    cudaFuncSetAttribute(k_temp, cudaFuncAttributeMaxDynamicSharedMemorySize, temp_smem);

    k_wprep<<<576, 256>>>(enc_re, enc_im, dec_re, dec_im, w1, w2, conv_w);
    k_setup<<<8, 256>>>(dt, lam_re, lam_im);
    k_sln<<<2048, 256>>>(x_real, x_imag, ln_s_w, ln_s_b);
    k_conv<<<dim3(32, 32), 256, conv_smem>>>(conv_b, x_real, x_imag);
    k_temp<<<dim3(512, 2), 512, temp_smem>>>(ln_t_w, ln_t_b, sb_re, sb_im,
                                             nz_r, nz_i, rw, rb, b1, b2, out);
}